// round 13
// baseline (speedup 1.0000x reference)
#include <cuda_runtime.h>
#include <cuda_fp16.h>
#include <math.h>
#include <stdint.h>

// ---------------------------------------------------------------------------
// Problem constants
// ---------------------------------------------------------------------------
#define BB 2
#define SS 1024
#define WW 64
#define PP (SS + WW - 1)   // 1087
#define EE 256
#define FIN 64
#define FF 1024
#define TE 768
#define NH 8
#define HD 32
#define NWIN (BB * SS)     // 2048
#define NROW (NWIN * WW)   // 131072
#define OUTD 10
#define LN_EPS 1e-5f
#define ATT_SCALE 0.17677669529663687f

// ---------------------------------------------------------------------------
// Scratch (fp32)
// ---------------------------------------------------------------------------
__device__ float g_emb  [BB * PP * EE];
__device__ float g_bufA [(size_t)NROW * EE];   // x1 / x2 (residual chain)
__device__ float g_xlast[NWIN * EE];
__device__ float g_r1   [NWIN * EE];
__device__ float g_r2   [NWIN * EE];

// Scratch (fp16)
__device__ __half g_in_h  [BB * SS * FIN];
__device__ __half g_ew_h  [EE * FIN];
__device__ __half g_qw_h  [2 * TE * EE];
__device__ __half g_aw_h  [2 * EE * EE];
__device__ __half g_f1w_h [2 * FF * EE];
__device__ __half g_f2w_h [2 * EE * FF];
__device__ __half g_emb_h [BB * PP * EE];
__device__ __half g_qkv_h [BB * PP * TE];
__device__ __half g_attn_h[(size_t)NROW * EE];
__device__ __half g_x_h   [(size_t)NROW * EE];
__device__ __half g_ffh_h [(size_t)NROW * FF];
__device__ __half g_kv2_h [(size_t)NROW * 512];
__device__ __half g_bufB_h[(size_t)NROW * EE];  // GEMM fp16 outputs -> add_ln
__device__ __half g_xlast_h[NWIN * EE];
__device__ __half g_r1_h  [NWIN * EE];
__device__ __half g_r3_h  [NWIN * FF];

// ---------------------------------------------------------------------------
// MMA helpers
// ---------------------------------------------------------------------------
__device__ __forceinline__ void mma_f16(float* c, const uint32_t* a, const uint32_t* b) {
    asm volatile(
        "mma.sync.aligned.m16n8k16.row.col.f32.f16.f16.f32 "
        "{%0,%1,%2,%3},{%4,%5,%6,%7},{%8,%9},{%0,%1,%2,%3};"
        : "+f"(c[0]), "+f"(c[1]), "+f"(c[2]), "+f"(c[3])
        : "r"(a[0]), "r"(a[1]), "r"(a[2]), "r"(a[3]), "r"(b[0]), "r"(b[1]));
}

__device__ __forceinline__ void cp16(void* s, const void* g) {
    uint32_t sa = (uint32_t)__cvta_generic_to_shared(s);
    asm volatile("cp.async.cg.shared.global [%0], [%1], 16;" :: "r"(sa), "l"(g));
}

__device__ __forceinline__ void ldsm4(uint32_t* r, uint32_t addr) {
    asm volatile("ldmatrix.sync.aligned.m8n8.x4.shared.b16 {%0,%1,%2,%3}, [%4];"
        : "=r"(r[0]), "=r"(r[1]), "=r"(r[2]), "=r"(r[3]) : "r"(addr));
}

// ---------------------------------------------------------------------------
// FP16 tensor-core GEMM (NT): C = act(A[M,K] * B[N,K]^T + bias)
// 128x128 tile, BK=64 (dynamic smem, 2-stage), cp.async overlap
// (commit prefetch t+1 BEFORE wait_group 1 -> load flies during MMA).
// Fragments via ldmatrix.x4. smem row stride 72 halves (144B): rows mod 8
// hit banks {0,4,..,28}+perm -> conflict-free LDSM.
// Requires: K % 64 == 0 or K == 64*T; N % 128 == 0.
// ---------------------------------------------------------------------------
#define HSM 72
#define HSTG (128 * HSM)          // halves per (array, stage)
#define TG_SMEM (4 * HSTG * 2)    // bytes total (A0,A1,B0,B1)

extern __shared__ __half hsm_[];

__global__ __launch_bounds__(256, 2) void tgemm_h(
    const __half* __restrict__ A, const __half* __restrict__ B,
    const float* __restrict__ bias, float* __restrict__ Cf,
    __half* __restrict__ Ch,
    int M, int N, int K, int lda, int ldb, int ldc, int act) {
    // layout: [A stage0][A stage1][B stage0][B stage1]
    __half* Asm = hsm_;
    __half* Bsm = hsm_ + 2 * HSTG;
    const int tid = threadIdx.x;
    const int bm = blockIdx.y * 128, bn = blockIdx.x * 128;
    const int lane = tid & 31, wid = tid >> 5;
    const int wm = (wid >> 2) * 64, wn = (wid & 3) * 32;
    const int g = lane >> 2, t4 = lane & 3;
    const int quad = lane >> 3, r8 = lane & 7;
    const int a_row = (quad & 1) * 8 + r8, a_colq = (quad >> 1) * 8;
    const int b_row = (quad >> 1) * 8 + r8, b_colq = (quad & 1) * 8;
    const uint32_t sA = (uint32_t)__cvta_generic_to_shared(Asm);
    const uint32_t sB = (uint32_t)__cvta_generic_to_shared(Bsm);

    float acc[4][4][4];
#pragma unroll
    for (int i = 0; i < 4; i++)
#pragma unroll
        for (int j = 0; j < 4; j++)
#pragma unroll
            for (int k = 0; k < 4; k++) acc[i][j][k] = 0.f;

    const int T = K / 64;
    const int lr = tid >> 1, lh = (tid & 1) * 32;
    int ga = bm + lr; if (ga >= M) ga = M - 1;
    const int gb = bn + lr;

    // prologue: tile 0
#pragma unroll
    for (int o = 0; o < 32; o += 8) {
        cp16(&Asm[lr * HSM + lh + o], A + (size_t)ga * lda + lh + o);
        cp16(&Bsm[lr * HSM + lh + o], B + (size_t)gb * ldb + lh + o);
    }
    asm volatile("cp.async.commit_group;");

    for (int t = 0; t < T; t++) {
        const int cur = t & 1;
        if (t + 1 < T) {
            const int k0 = (t + 1) * 64;
            const int nxt = cur ^ 1;
#pragma unroll
            for (int o = 0; o < 32; o += 8) {
                cp16(&Asm[nxt * HSTG + lr * HSM + lh + o], A + (size_t)ga * lda + k0 + lh + o);
                cp16(&Bsm[nxt * HSTG + lr * HSM + lh + o], B + (size_t)gb * ldb + k0 + lh + o);
            }
            asm volatile("cp.async.commit_group;");
            asm volatile("cp.async.wait_group 1;");
        } else {
            asm volatile("cp.async.wait_group 0;");
        }
        __syncthreads();

        const uint32_t aBase = sA + cur * (HSTG * 2);
        const uint32_t bBase = sB + cur * (HSTG * 2);
#pragma unroll
        for (int ks = 0; ks < 4; ks++) {
            const int kc = ks * 16;
            uint32_t af[4][4], bf[4][2];
#pragma unroll
            for (int mt = 0; mt < 4; mt++)
                ldsm4(af[mt], aBase + ((wm + mt * 16 + a_row) * HSM + kc + a_colq) * 2);
#pragma unroll
            for (int ntp = 0; ntp < 2; ntp++) {
                uint32_t bt[4];
                ldsm4(bt, bBase + ((wn + ntp * 16 + b_row) * HSM + kc + b_colq) * 2);
                bf[2 * ntp][0] = bt[0]; bf[2 * ntp][1] = bt[1];
                bf[2 * ntp + 1][0] = bt[2]; bf[2 * ntp + 1][1] = bt[3];
            }
#pragma unroll
            for (int mt = 0; mt < 4; mt++)
#pragma unroll
                for (int nt = 0; nt < 4; nt++)
                    mma_f16(acc[mt][nt], af[mt], bf[nt]);
        }
        __syncthreads();
    }

#pragma unroll
    for (int mt = 0; mt < 4; mt++) {
        const int rA = bm + wm + mt * 16 + g;
        const int rB = rA + 8;
#pragma unroll
        for (int nt = 0; nt < 4; nt++) {
            const int c = bn + wn + nt * 8 + 2 * t4;
            const float b0 = bias ? bias[c] : 0.f;
            const float b1 = bias ? bias[c + 1] : 0.f;
            float v0 = acc[mt][nt][0] + b0, v1 = acc[mt][nt][1] + b1;
            float v2 = acc[mt][nt][2] + b0, v3 = acc[mt][nt][3] + b1;
            if (act == 1) {
                v0 = v0 / (1.f + __expf(-v0));
                v1 = v1 / (1.f + __expf(-v1));
                v2 = v2 / (1.f + __expf(-v2));
                v3 = v3 / (1.f + __expf(-v3));
            }
            if (rA < M) {
                if (Cf) *(float2*)&Cf[(size_t)rA * ldc + c] = make_float2(v0, v1);
                if (Ch) *(__half2*)&Ch[(size_t)rA * ldc + c] = __floats2half2_rn(v0, v1);
            }
            if (rB < M) {
                if (Cf) *(float2*)&Cf[(size_t)rB * ldc + c] = make_float2(v2, v3);
                if (Ch) *(__half2*)&Ch[(size_t)rB * ldc + c] = __floats2half2_rn(v2, v3);
            }
        }
    }
}

// ---------------------------------------------------------------------------
// fp32 -> fp16 (vectorized)
// ---------------------------------------------------------------------------
__global__ void f2h2_kernel(const float2* __restrict__ src, __half2* __restrict__ dst, int n2) {
    int i = blockIdx.x * blockDim.x + threadIdx.x;
    if (i < n2) { float2 v = src[i]; dst[i] = __floats2half2_rn(v.x, v.y); }
}

// ---------------------------------------------------------------------------
// Zero pad rows of g_emb / g_emb_h
// ---------------------------------------------------------------------------
__global__ void zero_pad_kernel() {
    int idx = blockIdx.x * blockDim.x + threadIdx.x;
    if (idx >= BB * (WW - 1) * EE) return;
    int e = idx & (EE - 1);
    int p = (idx >> 8) % (WW - 1);
    int b = idx / ((WW - 1) * EE);
    size_t o = ((size_t)b * PP + p) * EE + e;
    g_emb[o] = 0.f;
    g_emb_h[o] = __float2half(0.f);
}

// ---------------------------------------------------------------------------
// Layer-1 attention, full fp16 MMA. One block (128 thr, 4 warps) per (n,h).
// ---------------------------------------------------------------------------
#define QS(r, c) s_q[(r) * 40 + (c)]
#define KS(r, c) s_k[(r) * 40 + (c)]
#define VT(d, c) s_vt[(d) * 72 + (c)]
#define SC(r, c) s_s[(r) * 66 + (c)]
#define PS(r, c) s_p[(r) * 72 + (c)]

__global__ __launch_bounds__(128) void attn1_kernel(const __half* __restrict__ qkv,
                                                    __half* __restrict__ out_h) {
    __shared__ __half s_q[WW * 40], s_k[WW * 40];
    __shared__ __half s_vt[HD * 72];
    __shared__ float  s_s[WW * 66];
    __shared__ __half s_p[WW * 72];
    const int h = blockIdx.x;
    const int n = blockIdx.y;
    const int b = n >> 10, s = n & (SS - 1);
    const int tid = threadIdx.x;
    const int lane = tid & 31, w = tid >> 5;
    const int g = lane >> 2, t4 = lane & 3;

    size_t base = ((size_t)b * PP + s) * TE + h * HD;
    for (int t = tid; t < WW * HD / 2; t += 128) {
        int wpos = t >> 4, wd = (t & 15) * 2;
        size_t r = base + (size_t)wpos * TE + wd;
        __half2 qv = *(const __half2*)&qkv[r];
        __half2 kv = *(const __half2*)&qkv[r + EE];
        __half2 vv = *(const __half2*)&qkv[r + 2 * EE];
        *(__half2*)&QS(wpos, wd) = qv;
        *(__half2*)&KS(wpos, wd) = kv;
        VT(wd, wpos) = vv.x;
        VT(wd + 1, wpos) = vv.y;
    }
    __syncthreads();

    {
        float sacc[8][4];
#pragma unroll
        for (int i = 0; i < 8; i++)
#pragma unroll
            for (int j = 0; j < 4; j++) sacc[i][j] = 0.f;
#pragma unroll
        for (int k0 = 0; k0 < HD; k0 += 16) {
            uint32_t a[4];
            a[0] = *(const uint32_t*)&QS(16 * w + g, k0 + 2 * t4);
            a[1] = *(const uint32_t*)&QS(16 * w + g + 8, k0 + 2 * t4);
            a[2] = *(const uint32_t*)&QS(16 * w + g, k0 + 8 + 2 * t4);
            a[3] = *(const uint32_t*)&QS(16 * w + g + 8, k0 + 8 + 2 * t4);
#pragma unroll
            for (int nt = 0; nt < 8; nt++) {
                uint32_t bfr[2];
                bfr[0] = *(const uint32_t*)&KS(nt * 8 + g, k0 + 2 * t4);
                bfr[1] = *(const uint32_t*)&KS(nt * 8 + g, k0 + 8 + 2 * t4);
                mma_f16(sacc[nt], a, bfr);
            }
        }
#pragma unroll
        for (int nt = 0; nt < 8; nt++) {
            const int r0 = 16 * w + g, c = nt * 8 + 2 * t4;
            *(float2*)&SC(r0, c)     = make_float2(sacc[nt][0] * ATT_SCALE, sacc[nt][1] * ATT_SCALE);
            *(float2*)&SC(r0 + 8, c) = make_float2(sacc[nt][2] * ATT_SCALE, sacc[nt][3] * ATT_SCALE);
        }
    }
    __syncthreads();

    {
        const int row = tid >> 1, half_ = tid & 1;
        const int cb = half_ * 32;
        float mx = -1e30f;
#pragma unroll
        for (int j = 0; j < 32; j++) mx = fmaxf(mx, SC(row, cb + j));
        mx = fmaxf(mx, __shfl_xor_sync(0xffffffff, mx, 1));
        float ebuf[32];
        float sum = 0.f;
#pragma unroll
        for (int j = 0; j < 32; j++) {
            ebuf[j] = __expf(SC(row, cb + j) - mx);
            sum += ebuf[j];
        }
        sum += __shfl_xor_sync(0xffffffff, sum, 1);
        float inv = 1.f / sum;
#pragma unroll
        for (int j = 0; j < 32; j++)
            PS(row, cb + j) = __float2half(ebuf[j] * inv);
    }
    __syncthreads();

    {
        float oacc[4][4];
#pragma unroll
        for (int i = 0; i < 4; i++)
#pragma unroll
            for (int j = 0; j < 4; j++) oacc[i][j] = 0.f;
#pragma unroll
        for (int k0 = 0; k0 < WW; k0 += 16) {
            uint32_t a[4];
            a[0] = *(const uint32_t*)&PS(16 * w + g, k0 + 2 * t4);
            a[1] = *(const uint32_t*)&PS(16 * w + g + 8, k0 + 2 * t4);
            a[2] = *(const uint32_t*)&PS(16 * w + g, k0 + 8 + 2 * t4);
            a[3] = *(const uint32_t*)&PS(16 * w + g + 8, k0 + 8 + 2 * t4);
#pragma unroll
            for (int nt = 0; nt < 4; nt++) {
                uint32_t bfr[2];
                bfr[0] = *(const uint32_t*)&VT(nt * 8 + g, k0 + 2 * t4);
                bfr[1] = *(const uint32_t*)&VT(nt * 8 + g, k0 + 8 + 2 * t4);
                mma_f16(oacc[nt], a, bfr);
            }
        }
        const size_t row0 = ((size_t)n * WW + 16 * w + g) * EE + h * HD;
        const size_t row1 = row0 + 8 * EE;
#pragma unroll
        for (int nt = 0; nt < 4; nt++) {
            const int c = nt * 8 + 2 * t4;
            *(__half2*)&out_h[row0 + c] = __floats2half2_rn(oacc[nt][0], oacc[nt][1]);
            *(__half2*)&out_h[row1 + c] = __floats2half2_rn(oacc[nt][2], oacc[nt][3]);
        }
    }
}

// ---------------------------------------------------------------------------
// Layer-2 attention (pruned): Q fp32 [2048,256], KV fp16 [NROW,512] -> fp16
// ---------------------------------------------------------------------------
__global__ __launch_bounds__(64) void attn2_kernel(const float* __restrict__ q2,
                                                   const __half* __restrict__ kv,
                                                   __half* __restrict__ out_h) {
    int h = blockIdx.x;
    int n = blockIdx.y;
    int tid = threadIdx.x;
    __shared__ float ks[WW][HD + 1], vs[WW][HD + 1];
    __shared__ float q[HD], p[WW];

    size_t base = (size_t)n * WW * 512 + h * HD;
    for (int t = tid; t < WW * HD; t += 64) {
        int wpos = t >> 5, d = t & 31;
        size_t r = base + (size_t)wpos * 512 + d;
        ks[wpos][d] = __half2float(kv[r]);
        vs[wpos][d] = __half2float(kv[r + 256]);
    }
    if (tid < HD) q[tid] = q2[(size_t)n * EE + h * HD + tid];
    __syncthreads();

    {
        float dsum = 0.f;
#pragma unroll
        for (int d = 0; d < HD; d++) dsum = fmaf(q[d], ks[tid][d], dsum);
        p[tid] = dsum * ATT_SCALE;
    }
    __syncthreads();
    if (tid < 32) {
        float v = fmaxf(p[tid], p[tid + 32]);
#pragma unroll
        for (int o = 16; o > 0; o >>= 1) v = fmaxf(v, __shfl_xor_sync(0xffffffff, v, o));
        float e0 = __expf(p[tid] - v), e1 = __expf(p[tid + 32] - v);
        float sm = e0 + e1;
#pragma unroll
        for (int o = 16; o > 0; o >>= 1) sm += __shfl_xor_sync(0xffffffff, sm, o);
        float inv = 1.f / sm;
        p[tid] = e0 * inv; p[tid + 32] = e1 * inv;
    }
    __syncthreads();
    if (tid < HD) {
        float acc = 0.f;
#pragma unroll
        for (int j = 0; j < WW; j++) acc = fmaf(p[j], vs[j][tid], acc);
        out_h[(size_t)n * EE + h * HD + tid] = __float2half(acc);
    }
}

// ---------------------------------------------------------------------------
// Fused residual-add + LayerNorm; a is fp16 (GEMM output), res fp32.
// mode 0: res row = row; mode 1: res = window view of g_emb.
// ---------------------------------------------------------------------------
__global__ __launch_bounds__(256) void add_ln_kernel(
    const __half* __restrict__ a, const float* __restrict__ res,
    const float* __restrict__ gamma, const float* __restrict__ beta,
    float* __restrict__ out, __half* __restrict__ out_h, int mode) {
    int row = blockIdx.x;
    int e = threadIdx.x;
    int lane = e & 31, w = e >> 5;
    __shared__ float ws[8];

    size_t roff;
    if (mode == 0) roff = (size_t)row * EE;
    else {
        int n = row >> 6, wp = row & 63;
        int b = n >> 10, s = n & (SS - 1);
        roff = ((size_t)b * PP + s + wp) * EE;
    }

    float x = __half2float(a[(size_t)row * EE + e]) + res[roff + e];

    float s1 = x;
#pragma unroll
    for (int o = 16; o > 0; o >>= 1) s1 += __shfl_xor_sync(0xffffffff, s1, o);
    if (lane == 0) ws[w] = s1;
    __syncthreads();
    float tot = 0.f;
#pragma unroll
    for (int i = 0; i < 8; i++) tot += ws[i];
    float mean = tot * (1.f / EE);
    __syncthreads();

    float d = x - mean;
    float s2 = d * d;
#pragma unroll
    for (int o = 16; o > 0; o >>= 1) s2 += __shfl_xor_sync(0xffffffff, s2, o);
    if (lane == 0) ws[w] = s2;
    __syncthreads();
    float tot2 = 0.f;
#pragma unroll
    for (int i = 0; i < 8; i++) tot2 += ws[i];
    float var = tot2 * (1.f / EE);
    float y = d * rsqrtf(var + LN_EPS) * gamma[e] + beta[e];
    out[(size_t)row * EE + e] = y;
    if (out_h) out_h[(size_t)row * EE + e] = __float2half(y);
}

// ---------------------------------------------------------------------------
// Gather last window rows -> fp32 + fp16
// ---------------------------------------------------------------------------
__global__ void gather_last_kernel(const float* __restrict__ x2,
                                   float* __restrict__ xlast,
                                   __half* __restrict__ xlast_h) {
    int idx = blockIdx.x * blockDim.x + threadIdx.x;
    if (idx >= NWIN * EE) return;
    int n = idx >> 8, e = idx & 255;
    float v = x2[((size_t)n * WW + (WW - 1)) * EE + e];
    xlast[idx] = v;
    xlast_h[idx] = __float2half(v);
}

// ---------------------------------------------------------------------------
// Head
// ---------------------------------------------------------------------------
__global__ void head_kernel(const float* __restrict__ y,
                            const float* __restrict__ hw,
                            const float* __restrict__ hb,
                            float* __restrict__ out) {
    int idx = blockIdx.x * blockDim.x + threadIdx.x;
    if (idx >= NWIN * OUTD) return;
    int n = idx / OUTD, o = idx % OUTD;
    const float* yr = y + (size_t)n * EE;
    const float* wr = hw + (size_t)o * EE;
    float acc = hb[o];
#pragma unroll 8
    for (int k = 0; k < EE; k++) acc = fmaf(yr[k], wr[k], acc);
    out[idx] = acc;
}

// ---------------------------------------------------------------------------
// Host launch
// ---------------------------------------------------------------------------
static inline dim3 tgrid(int M, int N) {
    return dim3(N / 128, (M + 127) / 128);
}
static inline void f2h(const float* s, __half* d, int n) {
    f2h2_kernel<<<(n / 2 + 255) / 256, 256>>>((const float2*)s, (__half2*)d, n / 2);
}

extern "C" void kernel_launch(void* const* d_in, const int* in_sizes, int n_in,
                              void* d_out, int out_size) {
    const float* inputs     = (const float*)d_in[0];
    const float* embed_w    = (const float*)d_in[1];
    const float* embed_b    = (const float*)d_in[2];
    const float* qkv_w      = (const float*)d_in[3];
    const float* qkv_b      = (const float*)d_in[4];
    const float* attn_out_w = (const float*)d_in[5];
    const float* attn_out_b = (const float*)d_in[6];
    const float* ln1_g      = (const float*)d_in[7];
    const float* ln1_b      = (const float*)d_in[8];
    const float* ffn1_w     = (const float*)d_in[9];
    const float* ffn1_b     = (const float*)d_in[10];
    const float* ffn2_w     = (const float*)d_in[11];
    const float* ffn2_b     = (const float*)d_in[12];
    const float* ln2_g      = (const float*)d_in[13];
    const float* ln2_b      = (const float*)d_in[14];
    const float* head_w     = (const float*)d_in[15];
    const float* head_b     = (const float*)d_in[16];
    float* out = (float*)d_out;

    cudaFuncSetAttribute(tgemm_h, cudaFuncAttributeMaxDynamicSharedMemorySize, TG_SMEM);

    float *emb, *bufA, *xlast, *r1, *r2;
    __half *in_h, *ew_h, *qw_h, *aw_h, *f1w_h, *f2w_h;
    __half *emb_h, *qkv_h, *attn_h, *x_h, *ffh_h, *kv2_h, *bufB_h, *xlast_h, *r1_h, *r3_h;
    cudaGetSymbolAddress((void**)&emb,   g_emb);
    cudaGetSymbolAddress((void**)&bufA,  g_bufA);
    cudaGetSymbolAddress((void**)&xlast, g_xlast);
    cudaGetSymbolAddress((void**)&r1,    g_r1);
    cudaGetSymbolAddress((void**)&r2,    g_r2);
    cudaGetSymbolAddress((void**)&in_h,   g_in_h);
    cudaGetSymbolAddress((void**)&ew_h,   g_ew_h);
    cudaGetSymbolAddress((void**)&qw_h,   g_qw_h);
    cudaGetSymbolAddress((void**)&aw_h,   g_aw_h);
    cudaGetSymbolAddress((void**)&f1w_h,  g_f1w_h);
    cudaGetSymbolAddress((void**)&f2w_h,  g_f2w_h);
    cudaGetSymbolAddress((void**)&emb_h,  g_emb_h);
    cudaGetSymbolAddress((void**)&qkv_h,  g_qkv_h);
    cudaGetSymbolAddress((void**)&attn_h, g_attn_h);
    cudaGetSymbolAddress((void**)&x_h,    g_x_h);
    cudaGetSymbolAddress((void**)&ffh_h,  g_ffh_h);
    cudaGetSymbolAddress((void**)&kv2_h,  g_kv2_h);
    cudaGetSymbolAddress((void**)&bufB_h, g_bufB_h);
    cudaGetSymbolAddress((void**)&xlast_h, g_xlast_h);
    cudaGetSymbolAddress((void**)&r1_h,   g_r1_h);
    cudaGetSymbolAddress((void**)&r3_h,   g_r3_h);

    // 0. fp16 conversions
    f2h(inputs,     in_h,  BB * SS * FIN);
    f2h(embed_w,    ew_h,  EE * FIN);
    f2h(qkv_w,      qw_h,  2 * TE * EE);
    f2h(attn_out_w, aw_h,  2 * EE * EE);
    f2h(ffn1_w,     f1w_h, 2 * FF * EE);
    f2h(ffn2_w,     f2w_h, 2 * EE * FF);
    zero_pad_kernel<<<(BB * (WW - 1) * EE + 255) / 256, 256>>>();

    // 1. embedding (per batch)
    for (int b = 0; b < BB; b++) {
        size_t off = ((size_t)b * PP + (WW - 1)) * EE;
        tgemm_h<<<tgrid(SS, EE), 256, TG_SMEM>>>(in_h + (size_t)b * SS * FIN, ew_h, embed_b,
                                                 emb + off, emb_h + off,
                                                 SS, EE, FIN, FIN, FIN, EE, 0);
    }
    // 2. Layer-1 QKV (shared) -> fp16
    tgemm_h<<<tgrid(BB * PP, TE), 256, TG_SMEM>>>(emb_h, qw_h, qkv_b, (float*)0, qkv_h,
                                                  BB * PP, TE, EE, EE, EE, TE, 0);
    // 3. attention -> fp16
    attn1_kernel<<<dim3(NH, NWIN), 128>>>(qkv_h, attn_h);
    // 4. attn-out proj -> fp16 bufB_h
    tgemm_h<<<tgrid(NROW, EE), 256, TG_SMEM>>>(attn_h, aw_h, attn_out_b, (float*)0, bufB_h,
                                               NROW, EE, EE, EE, EE, EE, 0);
    // 5. x1 = LN1(emb_window + bufB_h) -> bufA + x_h
    add_ln_kernel<<<NROW, 256>>>(bufB_h, emb, ln1_g, ln1_b, bufA, x_h, 1);
    // 6. FFN hidden (silu) -> fp16
    tgemm_h<<<tgrid(NROW, FF), 256, TG_SMEM>>>(x_h, f1w_h, ffn1_b, (float*)0, ffh_h,
                                               NROW, FF, EE, EE, EE, FF, 1);
    // 7. FFN out -> fp16 bufB_h
    tgemm_h<<<tgrid(NROW, EE), 256, TG_SMEM>>>(ffh_h, f2w_h, ffn2_b, (float*)0, bufB_h,
                                               NROW, EE, FF, FF, FF, EE, 0);
    // 8. x2 = LN2(x1 + bufB_h) -> bufA + x_h
    add_ln_kernel<<<NROW, 256>>>(bufB_h, bufA, ln2_g, ln2_b, bufA, x_h, 0);

    // ---- Layer 2 (output pruned) ----
    // 9. gather last rows; Q only for last rows -> fp32 r2
    gather_last_kernel<<<(NWIN * EE + 255) / 256, 256>>>(bufA, xlast, xlast_h);
    tgemm_h<<<tgrid(NWIN, EE), 256, TG_SMEM>>>(xlast_h, qw_h + (size_t)TE * EE, qkv_b + TE,
                                               r2, (__half*)0, NWIN, EE, EE, EE, EE, EE, 0);
    // 10. KV for all rows -> fp16 kv2_h
    tgemm_h<<<tgrid(NROW, 512), 256, TG_SMEM>>>(x_h, qw_h + (size_t)TE * EE + (size_t)EE * EE,
                                                qkv_b + TE + EE, (float*)0, kv2_h,
                                                NROW, 512, EE, EE, EE, 512, 0);
    // 11. attention -> fp16 r1_h
    attn2_kernel<<<dim3(NH, NWIN), 64>>>(r2, kv2_h, r1_h);
    // 12. proj -> fp16 bufB_h
    tgemm_h<<<tgrid(NWIN, EE), 256, TG_SMEM>>>(r1_h, aw_h + (size_t)EE * EE, attn_out_b + EE,
                                               (float*)0, bufB_h, NWIN, EE, EE, EE, EE, EE, 0);
    // 13. y = LN1_l2(xlast + bufB_h) -> r1 + r1_h
    add_ln_kernel<<<NWIN, 256>>>(bufB_h, xlast, ln1_g + EE, ln1_b + EE, r1, r1_h, 0);
    // 14. h2 = silu(y @ W1^T) -> fp16 r3_h
    tgemm_h<<<tgrid(NWIN, FF), 256, TG_SMEM>>>(r1_h, f1w_h + (size_t)FF * EE, ffn1_b + FF,
                                               (float*)0, r3_h, NWIN, FF, EE, EE, EE, FF, 1);
    // 15. f2 -> fp16 bufB_h
    tgemm_h<<<tgrid(NWIN, EE), 256, TG_SMEM>>>(r3_h, f2w_h + (size_t)EE * FF, ffn2_b + EE,
                                               (float*)0, bufB_h, NWIN, EE, FF, FF, FF, EE, 0);
    // 16. y2 = LN2_l2(y + f2) -> r1
    add_ln_kernel<<<NWIN, 256>>>(bufB_h, r1, ln2_g + EE, ln2_b + EE, r1, (__half*)0, 0);
    // 17. head -> d_out
    head_kernel<<<(NWIN * OUTD + 255) / 256, 256>>>(r1, head_w, head_b, out);
}

// round 14
// speedup vs baseline: 1.0524x; 1.0524x over previous
#include <cuda_runtime.h>
#include <cuda_fp16.h>
#include <math.h>
#include <stdint.h>

// ---------------------------------------------------------------------------
// Problem constants
// ---------------------------------------------------------------------------
#define BB 2
#define SS 1024
#define WW 64
#define PP (SS + WW - 1)   // 1087
#define EE 256
#define FIN 64
#define FF 1024
#define TE 768
#define NH 8
#define HD 32
#define NWIN (BB * SS)     // 2048
#define NROW (NWIN * WW)   // 131072
#define OUTD 10
#define LN_EPS 1e-5f
#define ATT_SCALE 0.17677669529663687f

// ---------------------------------------------------------------------------
// Scratch (fp32)
// ---------------------------------------------------------------------------
__device__ float g_emb  [BB * PP * EE];
__device__ float g_bufA [(size_t)NROW * EE];   // x1 / x2 (residual chain)
__device__ float g_xlast[NWIN * EE];
__device__ float g_r1   [NWIN * EE];
__device__ float g_r2   [NWIN * EE];

// Scratch (fp16)
__device__ __half g_in_h  [BB * SS * FIN];
__device__ __half g_ew_h  [EE * FIN];
__device__ __half g_qw_h  [2 * TE * EE];
__device__ __half g_aw_h  [2 * EE * EE];
__device__ __half g_f1w_h [2 * FF * EE];
__device__ __half g_f2w_h [2 * EE * FF];
__device__ __half g_emb_h [BB * PP * EE];
__device__ __half g_qkv_h [BB * PP * TE];
__device__ __half g_attn_h[(size_t)NROW * EE];
__device__ __half g_x_h   [(size_t)NROW * EE];
__device__ __half g_ffh_h [(size_t)NROW * FF];
__device__ __half g_kv2_h [(size_t)NROW * 512];
__device__ __half g_bufB_h[(size_t)NROW * EE];  // GEMM fp16 outputs -> add_ln
__device__ __half g_xlast_h[NWIN * EE];
__device__ __half g_r1_h  [NWIN * EE];
__device__ __half g_r3_h  [NWIN * FF];

// ---------------------------------------------------------------------------
// MMA helpers
// ---------------------------------------------------------------------------
__device__ __forceinline__ void mma_f16(float* c, const uint32_t* a, const uint32_t* b) {
    asm volatile(
        "mma.sync.aligned.m16n8k16.row.col.f32.f16.f16.f32 "
        "{%0,%1,%2,%3},{%4,%5,%6,%7},{%8,%9},{%0,%1,%2,%3};"
        : "+f"(c[0]), "+f"(c[1]), "+f"(c[2]), "+f"(c[3])
        : "r"(a[0]), "r"(a[1]), "r"(a[2]), "r"(a[3]), "r"(b[0]), "r"(b[1]));
}

__device__ __forceinline__ void cp16(void* s, const void* g) {
    uint32_t sa = (uint32_t)__cvta_generic_to_shared(s);
    asm volatile("cp.async.cg.shared.global [%0], [%1], 16;" :: "r"(sa), "l"(g));
}

__device__ __forceinline__ void ldsm4(uint32_t* r, uint32_t addr) {
    asm volatile("ldmatrix.sync.aligned.m8n8.x4.shared.b16 {%0,%1,%2,%3}, [%4];"
        : "=r"(r[0]), "=r"(r[1]), "=r"(r[2]), "=r"(r[3]) : "r"(addr));
}

// ---------------------------------------------------------------------------
// FP16 tensor-core GEMM (NT): C = act(A[M,K] * B[N,K]^T + bias)
// 128x128 tile, BK=32, double-buffered cp.async with load/compute overlap
// (commit prefetch t+1 BEFORE wait_group 1 -> load flies during MMA t).
// Fragments via ldmatrix.x4 (6 LDSM per 16 MMAs). smem row stride 40 halves
// (80B): 8 rows span all 32 banks exactly once -> conflict-free LDSM.
// Requires: K % 32 == 0, N % 128 == 0. Outputs: Cf (fp32) and/or Ch (fp16).
// ---------------------------------------------------------------------------
#define HBK 32
#define HSM 40
#define HBUF (128 * HSM * 2)   // bytes per stage

__global__ __launch_bounds__(256, 2) void tgemm_h(
    const __half* __restrict__ A, const __half* __restrict__ B,
    const float* __restrict__ bias, float* __restrict__ Cf,
    __half* __restrict__ Ch,
    int M, int N, int K, int lda, int ldb, int ldc, int act) {
    __shared__ __align__(16) __half As[2][128][HSM];
    __shared__ __align__(16) __half Bs[2][128][HSM];
    const int tid = threadIdx.x;
    const int bm = blockIdx.y * 128, bn = blockIdx.x * 128;
    const int lane = tid & 31, wid = tid >> 5;
    const int wm = (wid >> 2) * 64, wn = (wid & 3) * 32;
    const int g = lane >> 2, t4 = lane & 3;
    const int quad = lane >> 3, r8 = lane & 7;
    const int a_row = (quad & 1) * 8 + r8, a_colq = (quad >> 1) * 8;
    const int b_row = (quad >> 1) * 8 + r8, b_colq = (quad & 1) * 8;
    const uint32_t sA = (uint32_t)__cvta_generic_to_shared(&As[0][0][0]);
    const uint32_t sB = (uint32_t)__cvta_generic_to_shared(&Bs[0][0][0]);

    float acc[4][4][4];
#pragma unroll
    for (int i = 0; i < 4; i++)
#pragma unroll
        for (int j = 0; j < 4; j++)
#pragma unroll
            for (int k = 0; k < 4; k++) acc[i][j][k] = 0.f;

    const int T = K / HBK;
    const int lr = tid >> 1, lh = (tid & 1) * 16;
    int ga = bm + lr; if (ga >= M) ga = M - 1;
    const int gb = bn + lr;

    cp16(&As[0][lr][lh],     A + (size_t)ga * lda + lh);
    cp16(&As[0][lr][lh + 8], A + (size_t)ga * lda + lh + 8);
    cp16(&Bs[0][lr][lh],     B + (size_t)gb * ldb + lh);
    cp16(&Bs[0][lr][lh + 8], B + (size_t)gb * ldb + lh + 8);
    asm volatile("cp.async.commit_group;");

    for (int t = 0; t < T; t++) {
        const int cur = t & 1;
        if (t + 1 < T) {
            const int k0 = (t + 1) * HBK;
            const int nxt = cur ^ 1;
            cp16(&As[nxt][lr][lh],     A + (size_t)ga * lda + k0 + lh);
            cp16(&As[nxt][lr][lh + 8], A + (size_t)ga * lda + k0 + lh + 8);
            cp16(&Bs[nxt][lr][lh],     B + (size_t)gb * ldb + k0 + lh);
            cp16(&Bs[nxt][lr][lh + 8], B + (size_t)gb * ldb + k0 + lh + 8);
            asm volatile("cp.async.commit_group;");
            asm volatile("cp.async.wait_group 1;");
        } else {
            asm volatile("cp.async.wait_group 0;");
        }
        __syncthreads();

        const uint32_t aBase = sA + cur * HBUF;
        const uint32_t bBase = sB + cur * HBUF;
#pragma unroll
        for (int ks = 0; ks < 2; ks++) {
            const int kc = ks * 16;
            uint32_t af[4][4], bf[4][2];
#pragma unroll
            for (int mt = 0; mt < 4; mt++)
                ldsm4(af[mt], aBase + ((wm + mt * 16 + a_row) * HSM + kc + a_colq) * 2);
#pragma unroll
            for (int ntp = 0; ntp < 2; ntp++) {
                uint32_t bt[4];
                ldsm4(bt, bBase + ((wn + ntp * 16 + b_row) * HSM + kc + b_colq) * 2);
                bf[2 * ntp][0] = bt[0]; bf[2 * ntp][1] = bt[1];
                bf[2 * ntp + 1][0] = bt[2]; bf[2 * ntp + 1][1] = bt[3];
            }
#pragma unroll
            for (int mt = 0; mt < 4; mt++)
#pragma unroll
                for (int nt = 0; nt < 4; nt++)
                    mma_f16(acc[mt][nt], af[mt], bf[nt]);
        }
        __syncthreads();
    }

#pragma unroll
    for (int mt = 0; mt < 4; mt++) {
        const int rA = bm + wm + mt * 16 + g;
        const int rB = rA + 8;
#pragma unroll
        for (int nt = 0; nt < 4; nt++) {
            const int c = bn + wn + nt * 8 + 2 * t4;
            const float b0 = bias ? bias[c] : 0.f;
            const float b1 = bias ? bias[c + 1] : 0.f;
            float v0 = acc[mt][nt][0] + b0, v1 = acc[mt][nt][1] + b1;
            float v2 = acc[mt][nt][2] + b0, v3 = acc[mt][nt][3] + b1;
            if (act == 1) {
                v0 = v0 / (1.f + __expf(-v0));
                v1 = v1 / (1.f + __expf(-v1));
                v2 = v2 / (1.f + __expf(-v2));
                v3 = v3 / (1.f + __expf(-v3));
            }
            if (rA < M) {
                if (Cf) *(float2*)&Cf[(size_t)rA * ldc + c] = make_float2(v0, v1);
                if (Ch) *(__half2*)&Ch[(size_t)rA * ldc + c] = __floats2half2_rn(v0, v1);
            }
            if (rB < M) {
                if (Cf) *(float2*)&Cf[(size_t)rB * ldc + c] = make_float2(v2, v3);
                if (Ch) *(__half2*)&Ch[(size_t)rB * ldc + c] = __floats2half2_rn(v2, v3);
            }
        }
    }
}

// ---------------------------------------------------------------------------
// Fused fp32->fp16 for inputs + all weights (one launch, compile-time offsets)
// ---------------------------------------------------------------------------
#define N2_IN   (BB * SS * FIN / 2)        // 65536
#define N2_EW   (EE * FIN / 2)             // 8192
#define N2_QW   (2 * TE * EE / 2)          // 196608
#define N2_AW   (2 * EE * EE / 2)          // 65536
#define N2_F1W  (2 * FF * EE / 2)          // 262144
#define N2_F2W  (2 * EE * FF / 2)          // 262144
#define O_EW   (N2_IN)
#define O_QW   (O_EW + N2_EW)
#define O_AW   (O_QW + N2_QW)
#define O_F1W  (O_AW + N2_AW)
#define O_F2W  (O_F1W + N2_F1W)
#define N2_TOT (O_F2W + N2_F2W)            // 860160

__global__ void f2h_all_kernel(const float2* __restrict__ in,
                               const float2* __restrict__ ew,
                               const float2* __restrict__ qw,
                               const float2* __restrict__ aw,
                               const float2* __restrict__ f1w,
                               const float2* __restrict__ f2w) {
    int i = blockIdx.x * blockDim.x + threadIdx.x;
    if (i >= N2_TOT) return;
    const float2* src;
    __half2* dst;
    int o;
    if (i < O_EW)        { src = in;  dst = (__half2*)g_in_h;  o = i; }
    else if (i < O_QW)   { src = ew;  dst = (__half2*)g_ew_h;  o = i - O_EW; }
    else if (i < O_AW)   { src = qw;  dst = (__half2*)g_qw_h;  o = i - O_QW; }
    else if (i < O_F1W)  { src = aw;  dst = (__half2*)g_aw_h;  o = i - O_AW; }
    else if (i < O_F2W)  { src = f1w; dst = (__half2*)g_f1w_h; o = i - O_F1W; }
    else                 { src = f2w; dst = (__half2*)g_f2w_h; o = i - O_F2W; }
    float2 v = src[o];
    dst[o] = __floats2half2_rn(v.x, v.y);
}

// ---------------------------------------------------------------------------
// Zero pad rows of g_emb / g_emb_h
// ---------------------------------------------------------------------------
__global__ void zero_pad_kernel() {
    int idx = blockIdx.x * blockDim.x + threadIdx.x;
    if (idx >= BB * (WW - 1) * EE) return;
    int e = idx & (EE - 1);
    int p = (idx >> 8) % (WW - 1);
    int b = idx / ((WW - 1) * EE);
    size_t o = ((size_t)b * PP + p) * EE + e;
    g_emb[o] = 0.f;
    g_emb_h[o] = __float2half(0.f);
}

// ---------------------------------------------------------------------------
// Layer-1 attention, full fp16 MMA. One block (128 thr, 4 warps) per (n,h).
// ---------------------------------------------------------------------------
#define QS(r, c) s_q[(r) * 40 + (c)]
#define KS(r, c) s_k[(r) * 40 + (c)]
#define VT(d, c) s_vt[(d) * 72 + (c)]
#define SC(r, c) s_s[(r) * 66 + (c)]
#define PS(r, c) s_p[(r) * 72 + (c)]

__global__ __launch_bounds__(128) void attn1_kernel(const __half* __restrict__ qkv,
                                                    __half* __restrict__ out_h) {
    __shared__ __half s_q[WW * 40], s_k[WW * 40];
    __shared__ __half s_vt[HD * 72];
    __shared__ float  s_s[WW * 66];
    __shared__ __half s_p[WW * 72];
    const int h = blockIdx.x;
    const int n = blockIdx.y;
    const int b = n >> 10, s = n & (SS - 1);
    const int tid = threadIdx.x;
    const int lane = tid & 31, w = tid >> 5;
    const int g = lane >> 2, t4 = lane & 3;

    size_t base = ((size_t)b * PP + s) * TE + h * HD;
    for (int t = tid; t < WW * HD / 2; t += 128) {
        int wpos = t >> 4, wd = (t & 15) * 2;
        size_t r = base + (size_t)wpos * TE + wd;
        __half2 qv = *(const __half2*)&qkv[r];
        __half2 kv = *(const __half2*)&qkv[r + EE];
        __half2 vv = *(const __half2*)&qkv[r + 2 * EE];
        *(__half2*)&QS(wpos, wd) = qv;
        *(__half2*)&KS(wpos, wd) = kv;
        VT(wd, wpos) = vv.x;
        VT(wd + 1, wpos) = vv.y;
    }
    __syncthreads();

    {
        float sacc[8][4];
#pragma unroll
        for (int i = 0; i < 8; i++)
#pragma unroll
            for (int j = 0; j < 4; j++) sacc[i][j] = 0.f;
#pragma unroll
        for (int k0 = 0; k0 < HD; k0 += 16) {
            uint32_t a[4];
            a[0] = *(const uint32_t*)&QS(16 * w + g, k0 + 2 * t4);
            a[1] = *(const uint32_t*)&QS(16 * w + g + 8, k0 + 2 * t4);
            a[2] = *(const uint32_t*)&QS(16 * w + g, k0 + 8 + 2 * t4);
            a[3] = *(const uint32_t*)&QS(16 * w + g + 8, k0 + 8 + 2 * t4);
#pragma unroll
            for (int nt = 0; nt < 8; nt++) {
                uint32_t bfr[2];
                bfr[0] = *(const uint32_t*)&KS(nt * 8 + g, k0 + 2 * t4);
                bfr[1] = *(const uint32_t*)&KS(nt * 8 + g, k0 + 8 + 2 * t4);
                mma_f16(sacc[nt], a, bfr);
            }
        }
#pragma unroll
        for (int nt = 0; nt < 8; nt++) {
            const int r0 = 16 * w + g, c = nt * 8 + 2 * t4;
            *(float2*)&SC(r0, c)     = make_float2(sacc[nt][0] * ATT_SCALE, sacc[nt][1] * ATT_SCALE);
            *(float2*)&SC(r0 + 8, c) = make_float2(sacc[nt][2] * ATT_SCALE, sacc[nt][3] * ATT_SCALE);
        }
    }
    __syncthreads();

    {
        const int row = tid >> 1, half_ = tid & 1;
        const int cb = half_ * 32;
        float mx = -1e30f;
#pragma unroll
        for (int j = 0; j < 32; j++) mx = fmaxf(mx, SC(row, cb + j));
        mx = fmaxf(mx, __shfl_xor_sync(0xffffffff, mx, 1));
        float ebuf[32];
        float sum = 0.f;
#pragma unroll
        for (int j = 0; j < 32; j++) {
            ebuf[j] = __expf(SC(row, cb + j) - mx);
            sum += ebuf[j];
        }
        sum += __shfl_xor_sync(0xffffffff, sum, 1);
        float inv = 1.f / sum;
#pragma unroll
        for (int j = 0; j < 32; j++)
            PS(row, cb + j) = __float2half(ebuf[j] * inv);
    }
    __syncthreads();

    {
        float oacc[4][4];
#pragma unroll
        for (int i = 0; i < 4; i++)
#pragma unroll
            for (int j = 0; j < 4; j++) oacc[i][j] = 0.f;
#pragma unroll
        for (int k0 = 0; k0 < WW; k0 += 16) {
            uint32_t a[4];
            a[0] = *(const uint32_t*)&PS(16 * w + g, k0 + 2 * t4);
            a[1] = *(const uint32_t*)&PS(16 * w + g + 8, k0 + 2 * t4);
            a[2] = *(const uint32_t*)&PS(16 * w + g, k0 + 8 + 2 * t4);
            a[3] = *(const uint32_t*)&PS(16 * w + g + 8, k0 + 8 + 2 * t4);
#pragma unroll
            for (int nt = 0; nt < 4; nt++) {
                uint32_t bfr[2];
                bfr[0] = *(const uint32_t*)&VT(nt * 8 + g, k0 + 2 * t4);
                bfr[1] = *(const uint32_t*)&VT(nt * 8 + g, k0 + 8 + 2 * t4);
                mma_f16(oacc[nt], a, bfr);
            }
        }
        const size_t row0 = ((size_t)n * WW + 16 * w + g) * EE + h * HD;
        const size_t row1 = row0 + 8 * EE;
#pragma unroll
        for (int nt = 0; nt < 4; nt++) {
            const int c = nt * 8 + 2 * t4;
            *(__half2*)&out_h[row0 + c] = __floats2half2_rn(oacc[nt][0], oacc[nt][1]);
            *(__half2*)&out_h[row1 + c] = __floats2half2_rn(oacc[nt][2], oacc[nt][3]);
        }
    }
}

// ---------------------------------------------------------------------------
// Layer-2 attention (pruned): Q fp32 [2048,256], KV fp16 [NROW,512] -> fp16
// ---------------------------------------------------------------------------
__global__ __launch_bounds__(64) void attn2_kernel(const float* __restrict__ q2,
                                                   const __half* __restrict__ kv,
                                                   __half* __restrict__ out_h) {
    int h = blockIdx.x;
    int n = blockIdx.y;
    int tid = threadIdx.x;
    __shared__ float ks[WW][HD + 1], vs[WW][HD + 1];
    __shared__ float q[HD], p[WW];

    size_t base = (size_t)n * WW * 512 + h * HD;
    for (int t = tid; t < WW * HD; t += 64) {
        int wpos = t >> 5, d = t & 31;
        size_t r = base + (size_t)wpos * 512 + d;
        ks[wpos][d] = __half2float(kv[r]);
        vs[wpos][d] = __half2float(kv[r + 256]);
    }
    if (tid < HD) q[tid] = q2[(size_t)n * EE + h * HD + tid];
    __syncthreads();

    {
        float dsum = 0.f;
#pragma unroll
        for (int d = 0; d < HD; d++) dsum = fmaf(q[d], ks[tid][d], dsum);
        p[tid] = dsum * ATT_SCALE;
    }
    __syncthreads();
    if (tid < 32) {
        float v = fmaxf(p[tid], p[tid + 32]);
#pragma unroll
        for (int o = 16; o > 0; o >>= 1) v = fmaxf(v, __shfl_xor_sync(0xffffffff, v, o));
        float e0 = __expf(p[tid] - v), e1 = __expf(p[tid + 32] - v);
        float sm = e0 + e1;
#pragma unroll
        for (int o = 16; o > 0; o >>= 1) sm += __shfl_xor_sync(0xffffffff, sm, o);
        float inv = 1.f / sm;
        p[tid] = e0 * inv; p[tid + 32] = e1 * inv;
    }
    __syncthreads();
    if (tid < HD) {
        float acc = 0.f;
#pragma unroll
        for (int j = 0; j < WW; j++) acc = fmaf(p[j], vs[j][tid], acc);
        out_h[(size_t)n * EE + h * HD + tid] = __float2half(acc);
    }
}

// ---------------------------------------------------------------------------
// Fused residual-add + LayerNorm; a is fp16 (GEMM output), res fp32.
// mode 0: res row = row; mode 1: res = window view of g_emb.
// ---------------------------------------------------------------------------
__global__ __launch_bounds__(256) void add_ln_kernel(
    const __half* __restrict__ a, const float* __restrict__ res,
    const float* __restrict__ gamma, const float* __restrict__ beta,
    float* __restrict__ out, __half* __restrict__ out_h, int mode) {
    int row = blockIdx.x;
    int e = threadIdx.x;
    int lane = e & 31, w = e >> 5;
    __shared__ float ws[8];

    size_t roff;
    if (mode == 0) roff = (size_t)row * EE;
    else {
        int n = row >> 6, wp = row & 63;
        int b = n >> 10, s = n & (SS - 1);
        roff = ((size_t)b * PP + s + wp) * EE;
    }

    float x = __half2float(a[(size_t)row * EE + e]) + res[roff + e];

    float s1 = x;
#pragma unroll
    for (int o = 16; o > 0; o >>= 1) s1 += __shfl_xor_sync(0xffffffff, s1, o);
    if (lane == 0) ws[w] = s1;
    __syncthreads();
    float tot = 0.f;
#pragma unroll
    for (int i = 0; i < 8; i++) tot += ws[i];
    float mean = tot * (1.f / EE);
    __syncthreads();

    float d = x - mean;
    float s2 = d * d;
#pragma unroll
    for (int o = 16; o > 0; o >>= 1) s2 += __shfl_xor_sync(0xffffffff, s2, o);
    if (lane == 0) ws[w] = s2;
    __syncthreads();
    float tot2 = 0.f;
#pragma unroll
    for (int i = 0; i < 8; i++) tot2 += ws[i];
    float var = tot2 * (1.f / EE);
    float y = d * rsqrtf(var + LN_EPS) * gamma[e] + beta[e];
    out[(size_t)row * EE + e] = y;
    if (out_h) out_h[(size_t)row * EE + e] = __float2half(y);
}

// ---------------------------------------------------------------------------
// Gather last window rows -> fp32 + fp16
// ---------------------------------------------------------------------------
__global__ void gather_last_kernel(const float* __restrict__ x2,
                                   float* __restrict__ xlast,
                                   __half* __restrict__ xlast_h) {
    int idx = blockIdx.x * blockDim.x + threadIdx.x;
    if (idx >= NWIN * EE) return;
    int n = idx >> 8, e = idx & 255;
    float v = x2[((size_t)n * WW + (WW - 1)) * EE + e];
    xlast[idx] = v;
    xlast_h[idx] = __float2half(v);
}

// ---------------------------------------------------------------------------
// Head
// ---------------------------------------------------------------------------
__global__ void head_kernel(const float* __restrict__ y,
                            const float* __restrict__ hw,
                            const float* __restrict__ hb,
                            float* __restrict__ out) {
    int idx = blockIdx.x * blockDim.x + threadIdx.x;
    if (idx >= NWIN * OUTD) return;
    int n = idx / OUTD, o = idx % OUTD;
    const float* yr = y + (size_t)n * EE;
    const float* wr = hw + (size_t)o * EE;
    float acc = hb[o];
#pragma unroll 8
    for (int k = 0; k < EE; k++) acc = fmaf(yr[k], wr[k], acc);
    out[idx] = acc;
}

// ---------------------------------------------------------------------------
// Host launch
// ---------------------------------------------------------------------------
static inline dim3 tgrid(int M, int N) {
    return dim3(N / 128, (M + 127) / 128);
}

extern "C" void kernel_launch(void* const* d_in, const int* in_sizes, int n_in,
                              void* d_out, int out_size) {
    const float* inputs     = (const float*)d_in[0];
    const float* embed_w    = (const float*)d_in[1];
    const float* embed_b    = (const float*)d_in[2];
    const float* qkv_w      = (const float*)d_in[3];
    const float* qkv_b      = (const float*)d_in[4];
    const float* attn_out_w = (const float*)d_in[5];
    const float* attn_out_b = (const float*)d_in[6];
    const float* ln1_g      = (const float*)d_in[7];
    const float* ln1_b      = (const float*)d_in[8];
    const float* ffn1_w     = (const float*)d_in[9];
    const float* ffn1_b     = (const float*)d_in[10];
    const float* ffn2_w     = (const float*)d_in[11];
    const float* ffn2_b     = (const float*)d_in[12];
    const float* ln2_g      = (const float*)d_in[13];
    const float* ln2_b      = (const float*)d_in[14];
    const float* head_w     = (const float*)d_in[15];
    const float* head_b     = (const float*)d_in[16];
    float* out = (float*)d_out;

    float *emb, *bufA, *xlast, *r1, *r2;
    __half *ew_h, *qw_h, *aw_h, *f1w_h, *f2w_h, *in_h;
    __half *emb_h, *qkv_h, *attn_h, *x_h, *ffh_h, *kv2_h, *bufB_h, *xlast_h, *r1_h, *r3_h;
    cudaGetSymbolAddress((void**)&emb,   g_emb);
    cudaGetSymbolAddress((void**)&bufA,  g_bufA);
    cudaGetSymbolAddress((void**)&xlast, g_xlast);
    cudaGetSymbolAddress((void**)&r1,    g_r1);
    cudaGetSymbolAddress((void**)&r2,    g_r2);
    cudaGetSymbolAddress((void**)&in_h,   g_in_h);
    cudaGetSymbolAddress((void**)&ew_h,   g_ew_h);
    cudaGetSymbolAddress((void**)&qw_h,   g_qw_h);
    cudaGetSymbolAddress((void**)&aw_h,   g_aw_h);
    cudaGetSymbolAddress((void**)&f1w_h,  g_f1w_h);
    cudaGetSymbolAddress((void**)&f2w_h,  g_f2w_h);
    cudaGetSymbolAddress((void**)&emb_h,  g_emb_h);
    cudaGetSymbolAddress((void**)&qkv_h,  g_qkv_h);
    cudaGetSymbolAddress((void**)&attn_h, g_attn_h);
    cudaGetSymbolAddress((void**)&x_h,    g_x_h);
    cudaGetSymbolAddress((void**)&ffh_h,  g_ffh_h);
    cudaGetSymbolAddress((void**)&kv2_h,  g_kv2_h);
    cudaGetSymbolAddress((void**)&bufB_h, g_bufB_h);
    cudaGetSymbolAddress((void**)&xlast_h, g_xlast_h);
    cudaGetSymbolAddress((void**)&r1_h,   g_r1_h);
    cudaGetSymbolAddress((void**)&r3_h,   g_r3_h);

    // 0. fused fp16 conversions (1 launch) + pad zeroing
    f2h_all_kernel<<<(N2_TOT + 255) / 256, 256>>>(
        (const float2*)inputs, (const float2*)embed_w, (const float2*)qkv_w,
        (const float2*)attn_out_w, (const float2*)ffn1_w, (const float2*)ffn2_w);
    zero_pad_kernel<<<(BB * (WW - 1) * EE + 255) / 256, 256>>>();

    // 1. embedding (per batch)
    for (int b = 0; b < BB; b++) {
        size_t off = ((size_t)b * PP + (WW - 1)) * EE;
        tgemm_h<<<tgrid(SS, EE), 256>>>(in_h + (size_t)b * SS * FIN, ew_h, embed_b,
                                        emb + off, emb_h + off,
                                        SS, EE, FIN, FIN, FIN, EE, 0);
    }
    // 2. Layer-1 QKV (shared) -> fp16
    tgemm_h<<<tgrid(BB * PP, TE), 256>>>(emb_h, qw_h, qkv_b, (float*)0, qkv_h,
                                         BB * PP, TE, EE, EE, EE, TE, 0);
    // 3. attention -> fp16
    attn1_kernel<<<dim3(NH, NWIN), 128>>>(qkv_h, attn_h);
    // 4. attn-out proj -> fp16 bufB_h
    tgemm_h<<<tgrid(NROW, EE), 256>>>(attn_h, aw_h, attn_out_b, (float*)0, bufB_h,
                                      NROW, EE, EE, EE, EE, EE, 0);
    // 5. x1 = LN1(emb_window + bufB_h) -> bufA + x_h
    add_ln_kernel<<<NROW, 256>>>(bufB_h, emb, ln1_g, ln1_b, bufA, x_h, 1);
    // 6. FFN hidden (silu) -> fp16
    tgemm_h<<<tgrid(NROW, FF), 256>>>(x_h, f1w_h, ffn1_b, (float*)0, ffh_h,
                                      NROW, FF, EE, EE, EE, FF, 1);
    // 7. FFN out -> fp16 bufB_h
    tgemm_h<<<tgrid(NROW, EE), 256>>>(ffh_h, f2w_h, ffn2_b, (float*)0, bufB_h,
                                      NROW, EE, FF, FF, FF, EE, 0);
    // 8. x2 = LN2(x1 + bufB_h) -> bufA + x_h
    add_ln_kernel<<<NROW, 256>>>(bufB_h, bufA, ln2_g, ln2_b, bufA, x_h, 0);

    // ---- Layer 2 (output pruned) ----
    // 9. gather last rows; Q only for last rows -> fp32 r2
    gather_last_kernel<<<(NWIN * EE + 255) / 256, 256>>>(bufA, xlast, xlast_h);
    tgemm_h<<<tgrid(NWIN, EE), 256>>>(xlast_h, qw_h + (size_t)TE * EE, qkv_b + TE,
                                      r2, (__half*)0, NWIN, EE, EE, EE, EE, EE, 0);
    // 10. KV for all rows -> fp16 kv2_h
    tgemm_h<<<tgrid(NROW, 512), 256>>>(x_h, qw_h + (size_t)TE * EE + (size_t)EE * EE,
                                       qkv_b + TE + EE, (float*)0, kv2_h,
                                       NROW, 512, EE, EE, EE, 512, 0);
    // 11. attention -> fp16 r1_h
    attn2_kernel<<<dim3(NH, NWIN), 64>>>(r2, kv2_h, r1_h);
    // 12. proj -> fp16 bufB_h
    tgemm_h<<<tgrid(NWIN, EE), 256>>>(r1_h, aw_h + (size_t)EE * EE, attn_out_b + EE,
                                      (float*)0, bufB_h, NWIN, EE, EE, EE, EE, EE, 0);
    // 13. y = LN1_l2(xlast + bufB_h) -> r1 + r1_h
    add_ln_kernel<<<NWIN, 256>>>(bufB_h, xlast, ln1_g + EE, ln1_b + EE, r1, r1_h, 0);
    // 14. h2 = silu(y @ W1^T) -> fp16 r3_h
    tgemm_h<<<tgrid(NWIN, FF), 256>>>(r1_h, f1w_h + (size_t)FF * EE, ffn1_b + FF,
                                      (float*)0, r3_h, NWIN, FF, EE, EE, EE, FF, 1);
    // 15. f2 -> fp16 bufB_h
    tgemm_h<<<tgrid(NWIN, EE), 256>>>(r3_h, f2w_h + (size_t)EE * FF, ffn2_b + EE,
                                      (float*)0, bufB_h, NWIN, EE, FF, FF, FF, EE, 0);
    // 16. y2 = LN2_l2(y + f2) -> r1
    add_ln_kernel<<<NWIN, 256>>>(bufB_h, r1, ln2_g + EE, ln2_b + EE, r1, (__half*)0, 0);
    // 17. head -> d_out
    head_kernel<<<(NWIN * OUTD + 255) / 256, 256>>>(r1, head_w, head_b, out);
}

// round 15
// speedup vs baseline: 1.0772x; 1.0236x over previous
#include <cuda_runtime.h>
#include <cuda_fp16.h>
#include <math.h>
#include <stdint.h>

// ---------------------------------------------------------------------------
// Problem constants
// ---------------------------------------------------------------------------
#define BB 2
#define SS 1024
#define WW 64
#define PP (SS + WW - 1)   // 1087
#define EE 256
#define FIN 64
#define FF 1024
#define TE 768
#define NH 8
#define HD 32
#define NWIN (BB * SS)     // 2048
#define NROW (NWIN * WW)   // 131072
#define OUTD 10
#define LN_EPS 1e-5f
#define ATT_SCALE 0.17677669529663687f

// ---------------------------------------------------------------------------
// Scratch (fp32)
// ---------------------------------------------------------------------------
__device__ float g_emb  [BB * PP * EE];
__device__ float g_bufA [(size_t)NROW * EE];   // x1 / x2 (residual chain)
__device__ float g_xlast[NWIN * EE];
__device__ float g_r1   [NWIN * EE];
__device__ float g_r2   [NWIN * EE];

// Scratch (fp16)
__device__ __half g_in_h  [BB * SS * FIN];
__device__ __half g_ew_h  [EE * FIN];
__device__ __half g_qw_h  [2 * TE * EE];
__device__ __half g_aw_h  [2 * EE * EE];
__device__ __half g_f1w_h [2 * FF * EE];
__device__ __half g_f2w_h [2 * EE * FF];
__device__ __half g_emb_h [BB * PP * EE];
__device__ __half g_qkv_h [BB * PP * TE];
__device__ __half g_attn_h[(size_t)NROW * EE];
__device__ __half g_x_h   [(size_t)NROW * EE];
__device__ __half g_ffh_h [(size_t)NROW * FF];
__device__ __half g_kv2_h [(size_t)NROW * 512];
__device__ __half g_xlast_h[NWIN * EE];
__device__ __half g_r1_h  [NWIN * EE];
__device__ __half g_r3_h  [NWIN * FF];

// ---------------------------------------------------------------------------
// MMA helpers
// ---------------------------------------------------------------------------
__device__ __forceinline__ void mma_f16(float* c, const uint32_t* a, const uint32_t* b) {
    asm volatile(
        "mma.sync.aligned.m16n8k16.row.col.f32.f16.f16.f32 "
        "{%0,%1,%2,%3},{%4,%5,%6,%7},{%8,%9},{%0,%1,%2,%3};"
        : "+f"(c[0]), "+f"(c[1]), "+f"(c[2]), "+f"(c[3])
        : "r"(a[0]), "r"(a[1]), "r"(a[2]), "r"(a[3]), "r"(b[0]), "r"(b[1]));
}

__device__ __forceinline__ void cp16(void* s, const void* g) {
    uint32_t sa = (uint32_t)__cvta_generic_to_shared(s);
    asm volatile("cp.async.cg.shared.global [%0], [%1], 16;" :: "r"(sa), "l"(g));
}

__device__ __forceinline__ void ldsm4(uint32_t* r, uint32_t addr) {
    asm volatile("ldmatrix.sync.aligned.m8n8.x4.shared.b16 {%0,%1,%2,%3}, [%4];"
        : "=r"(r[0]), "=r"(r[1]), "=r"(r[2]), "=r"(r[3]) : "r"(addr));
}

// ---------------------------------------------------------------------------
// FP16 tensor-core GEMM (NT): C = act(A[M,K] * B[N,K]^T + bias)  [R12 proven]
// 128x128 tile, BK=32, double-buffered cp.async with load/compute overlap.
// ---------------------------------------------------------------------------
#define HBK 32
#define HSM 40
#define HBUF (128 * HSM * 2)   // bytes per stage

__global__ __launch_bounds__(256, 2) void tgemm_h(
    const __half* __restrict__ A, const __half* __restrict__ B,
    const float* __restrict__ bias, float* __restrict__ Cf,
    __half* __restrict__ Ch,
    int M, int N, int K, int lda, int ldb, int ldc, int act) {
    __shared__ __align__(16) __half As[2][128][HSM];
    __shared__ __align__(16) __half Bs[2][128][HSM];
    const int tid = threadIdx.x;
    const int bm = blockIdx.y * 128, bn = blockIdx.x * 128;
    const int lane = tid & 31, wid = tid >> 5;
    const int wm = (wid >> 2) * 64, wn = (wid & 3) * 32;
    const int g = lane >> 2, t4 = lane & 3;
    const int quad = lane >> 3, r8 = lane & 7;
    const int a_row = (quad & 1) * 8 + r8, a_colq = (quad >> 1) * 8;
    const int b_row = (quad >> 1) * 8 + r8, b_colq = (quad & 1) * 8;
    const uint32_t sA = (uint32_t)__cvta_generic_to_shared(&As[0][0][0]);
    const uint32_t sB = (uint32_t)__cvta_generic_to_shared(&Bs[0][0][0]);

    float acc[4][4][4];
#pragma unroll
    for (int i = 0; i < 4; i++)
#pragma unroll
        for (int j = 0; j < 4; j++)
#pragma unroll
            for (int k = 0; k < 4; k++) acc[i][j][k] = 0.f;

    const int T = K / HBK;
    const int lr = tid >> 1, lh = (tid & 1) * 16;
    int ga = bm + lr; if (ga >= M) ga = M - 1;
    const int gb = bn + lr;

    cp16(&As[0][lr][lh],     A + (size_t)ga * lda + lh);
    cp16(&As[0][lr][lh + 8], A + (size_t)ga * lda + lh + 8);
    cp16(&Bs[0][lr][lh],     B + (size_t)gb * ldb + lh);
    cp16(&Bs[0][lr][lh + 8], B + (size_t)gb * ldb + lh + 8);
    asm volatile("cp.async.commit_group;");

    for (int t = 0; t < T; t++) {
        const int cur = t & 1;
        if (t + 1 < T) {
            const int k0 = (t + 1) * HBK;
            const int nxt = cur ^ 1;
            cp16(&As[nxt][lr][lh],     A + (size_t)ga * lda + k0 + lh);
            cp16(&As[nxt][lr][lh + 8], A + (size_t)ga * lda + k0 + lh + 8);
            cp16(&Bs[nxt][lr][lh],     B + (size_t)gb * ldb + k0 + lh);
            cp16(&Bs[nxt][lr][lh + 8], B + (size_t)gb * ldb + k0 + lh + 8);
            asm volatile("cp.async.commit_group;");
            asm volatile("cp.async.wait_group 1;");
        } else {
            asm volatile("cp.async.wait_group 0;");
        }
        __syncthreads();

        const uint32_t aBase = sA + cur * HBUF;
        const uint32_t bBase = sB + cur * HBUF;
#pragma unroll
        for (int ks = 0; ks < 2; ks++) {
            const int kc = ks * 16;
            uint32_t af[4][4], bf[4][2];
#pragma unroll
            for (int mt = 0; mt < 4; mt++)
                ldsm4(af[mt], aBase + ((wm + mt * 16 + a_row) * HSM + kc + a_colq) * 2);
#pragma unroll
            for (int ntp = 0; ntp < 2; ntp++) {
                uint32_t bt[4];
                ldsm4(bt, bBase + ((wn + ntp * 16 + b_row) * HSM + kc + b_colq) * 2);
                bf[2 * ntp][0] = bt[0]; bf[2 * ntp][1] = bt[1];
                bf[2 * ntp + 1][0] = bt[2]; bf[2 * ntp + 1][1] = bt[3];
            }
#pragma unroll
            for (int mt = 0; mt < 4; mt++)
#pragma unroll
                for (int nt = 0; nt < 4; nt++)
                    mma_f16(acc[mt][nt], af[mt], bf[nt]);
        }
        __syncthreads();
    }

#pragma unroll
    for (int mt = 0; mt < 4; mt++) {
        const int rA = bm + wm + mt * 16 + g;
        const int rB = rA + 8;
#pragma unroll
        for (int nt = 0; nt < 4; nt++) {
            const int c = bn + wn + nt * 8 + 2 * t4;
            const float b0 = bias ? bias[c] : 0.f;
            const float b1 = bias ? bias[c + 1] : 0.f;
            float v0 = acc[mt][nt][0] + b0, v1 = acc[mt][nt][1] + b1;
            float v2 = acc[mt][nt][2] + b0, v3 = acc[mt][nt][3] + b1;
            if (act == 1) {
                v0 = v0 / (1.f + __expf(-v0));
                v1 = v1 / (1.f + __expf(-v1));
                v2 = v2 / (1.f + __expf(-v2));
                v3 = v3 / (1.f + __expf(-v3));
            }
            if (rA < M) {
                if (Cf) *(float2*)&Cf[(size_t)rA * ldc + c] = make_float2(v0, v1);
                if (Ch) *(__half2*)&Ch[(size_t)rA * ldc + c] = __floats2half2_rn(v0, v1);
            }
            if (rB < M) {
                if (Cf) *(float2*)&Cf[(size_t)rB * ldc + c] = make_float2(v2, v3);
                if (Ch) *(__half2*)&Ch[(size_t)rB * ldc + c] = __floats2half2_rn(v2, v3);
            }
        }
    }
}

// ---------------------------------------------------------------------------
// Fused GEMM (NT, N=256 full width) + bias + residual-add + LayerNorm.
// Tile 128 x 256, 8 warps (2M x 4N), each warp iterates 2 column halves.
// Same k-loop skeleton as tgemm_h. After GEMM: fp16 C tile in smem (identical
// numerics to the old bufB_h round trip), then per-warp row LN with gmem
// residual. Outputs: fp32 out, optional fp16 out_h.
// mode 0: residual row = global row; mode 1: residual = g_emb window view.
// ---------------------------------------------------------------------------
#define FSM 40
#define F_ASTG (128 * FSM)   // halves per A stage
#define F_BSTG (256 * FSM)   // halves per B stage
#define F_CSM 264            // C tile row stride (halves)
#define F_SMEM_BYTES (128 * F_CSM * 2 > 2 * (F_ASTG + F_BSTG) * 2 ? 128 * F_CSM * 2 : 2 * (F_ASTG + F_BSTG) * 2)

extern __shared__ __half fsm_[];

__global__ __launch_bounds__(256, 1) void tgemm_ln(
    const __half* __restrict__ A, const __half* __restrict__ B,
    const float* __restrict__ bias, const float* __restrict__ res,
    const float* __restrict__ gamma, const float* __restrict__ beta,
    float* __restrict__ out, __half* __restrict__ out_h,
    int M, int K, int lda, int ldb, int mode) {
    __half* Asm = fsm_;                       // [2][128][FSM]
    __half* Bsm = fsm_ + 2 * F_ASTG;          // [2][256][FSM]
    __half* Csm = fsm_;                       // reused post-GEMM: [128][F_CSM]
    const int tid = threadIdx.x;
    const int bm = blockIdx.x * 128;
    const int lane = tid & 31, wid = tid >> 5;
    const int wm = (wid >> 2) * 64, wnb = (wid & 3) * 32;
    const int g = lane >> 2, t4 = lane & 3;
    const int quad = lane >> 3, r8 = lane & 7;
    const int a_row = (quad & 1) * 8 + r8, a_colq = (quad >> 1) * 8;
    const int b_row = (quad >> 1) * 8 + r8, b_colq = (quad & 1) * 8;
    const uint32_t sA = (uint32_t)__cvta_generic_to_shared(Asm);
    const uint32_t sB = (uint32_t)__cvta_generic_to_shared(Bsm);

    float acc[2][4][4][4];
#pragma unroll
    for (int hh = 0; hh < 2; hh++)
#pragma unroll
        for (int i = 0; i < 4; i++)
#pragma unroll
            for (int j = 0; j < 4; j++)
#pragma unroll
                for (int k = 0; k < 4; k++) acc[hh][i][j][k] = 0.f;

    const int T = K / HBK;
    const int lr = tid >> 1, lh = (tid & 1) * 16;
    int ga = bm + lr; if (ga >= M) ga = M - 1;

    // prologue: tile 0 (A: 2 cp16/thread; B: row tid, 4 cp16/thread)
    cp16(&Asm[lr * FSM + lh],     A + (size_t)ga * lda + lh);
    cp16(&Asm[lr * FSM + lh + 8], A + (size_t)ga * lda + lh + 8);
#pragma unroll
    for (int o = 0; o < 32; o += 8)
        cp16(&Bsm[tid * FSM + o], B + (size_t)tid * ldb + o);
    asm volatile("cp.async.commit_group;");

    for (int t = 0; t < T; t++) {
        const int cur = t & 1;
        if (t + 1 < T) {
            const int k0 = (t + 1) * HBK;
            const int nxt = cur ^ 1;
            cp16(&Asm[nxt * F_ASTG + lr * FSM + lh],     A + (size_t)ga * lda + k0 + lh);
            cp16(&Asm[nxt * F_ASTG + lr * FSM + lh + 8], A + (size_t)ga * lda + k0 + lh + 8);
#pragma unroll
            for (int o = 0; o < 32; o += 8)
                cp16(&Bsm[nxt * F_BSTG + tid * FSM + o], B + (size_t)tid * ldb + k0 + o);
            asm volatile("cp.async.commit_group;");
            asm volatile("cp.async.wait_group 1;");
        } else {
            asm volatile("cp.async.wait_group 0;");
        }
        __syncthreads();

        const uint32_t aBase = sA + cur * (F_ASTG * 2);
        const uint32_t bBase = sB + cur * (F_BSTG * 2);
#pragma unroll
        for (int ks = 0; ks < 2; ks++) {
            const int kc = ks * 16;
            uint32_t af[4][4];
#pragma unroll
            for (int mt = 0; mt < 4; mt++)
                ldsm4(af[mt], aBase + ((wm + mt * 16 + a_row) * FSM + kc + a_colq) * 2);
#pragma unroll
            for (int hh = 0; hh < 2; hh++) {
                const int col0 = hh * 128 + wnb;
                uint32_t bf[4][2];
#pragma unroll
                for (int ntp = 0; ntp < 2; ntp++) {
                    uint32_t bt[4];
                    ldsm4(bt, bBase + ((col0 + ntp * 16 + b_row) * FSM + kc + b_colq) * 2);
                    bf[2 * ntp][0] = bt[0]; bf[2 * ntp][1] = bt[1];
                    bf[2 * ntp + 1][0] = bt[2]; bf[2 * ntp + 1][1] = bt[3];
                }
#pragma unroll
                for (int mt = 0; mt < 4; mt++)
#pragma unroll
                    for (int nt = 0; nt < 4; nt++)
                        mma_f16(acc[hh][mt][nt], af[mt], bf[nt]);
            }
        }
        __syncthreads();
    }

    // stage smem no longer needed -> store fp16 C tile (bias added)
#pragma unroll
    for (int hh = 0; hh < 2; hh++)
#pragma unroll
        for (int mt = 0; mt < 4; mt++) {
            const int r0 = wm + mt * 16 + g;
#pragma unroll
            for (int nt = 0; nt < 4; nt++) {
                const int c = hh * 128 + wnb + nt * 8 + 2 * t4;
                const float b0 = bias[c], b1 = bias[c + 1];
                *(__half2*)&Csm[r0 * F_CSM + c] =
                    __floats2half2_rn(acc[hh][mt][nt][0] + b0, acc[hh][mt][nt][1] + b1);
                *(__half2*)&Csm[(r0 + 8) * F_CSM + c] =
                    __floats2half2_rn(acc[hh][mt][nt][2] + b0, acc[hh][mt][nt][3] + b1);
            }
        }
    __syncthreads();

    // LN phase: warp wid handles rows wid*16 .. wid*16+15; lane covers 8 cols
    const int c0 = lane * 8;
    for (int i = 0; i < 16; i++) {
        const int row = wid * 16 + i;
        const int gr = bm + row;
        if (gr >= M) break;
        size_t roff;
        if (mode == 0) roff = (size_t)gr * EE;
        else {
            int n = gr >> 6, wp = gr & 63;
            int b = n >> 10, s = n & (SS - 1);
            roff = ((size_t)b * PP + s + wp) * EE;
        }
        // load 8 C halves + 8 residual floats
        uint4 cv = *(uint4*)&Csm[row * F_CSM + c0];
        __half2 ch[4];
        ch[0] = *(__half2*)&cv.x; ch[1] = *(__half2*)&cv.y;
        ch[2] = *(__half2*)&cv.z; ch[3] = *(__half2*)&cv.w;
        float4 rv0 = *(const float4*)&res[roff + c0];
        float4 rv1 = *(const float4*)&res[roff + c0 + 4];
        float xv[8];
        xv[0] = __half2float(ch[0].x) + rv0.x; xv[1] = __half2float(ch[0].y) + rv0.y;
        xv[2] = __half2float(ch[1].x) + rv0.z; xv[3] = __half2float(ch[1].y) + rv0.w;
        xv[4] = __half2float(ch[2].x) + rv1.x; xv[5] = __half2float(ch[2].y) + rv1.y;
        xv[6] = __half2float(ch[3].x) + rv1.z; xv[7] = __half2float(ch[3].y) + rv1.w;
        float s1 = 0.f;
#pragma unroll
        for (int j = 0; j < 8; j++) s1 += xv[j];
#pragma unroll
        for (int o = 16; o > 0; o >>= 1) s1 += __shfl_xor_sync(0xffffffff, s1, o);
        const float mean = s1 * (1.f / EE);
        float s2 = 0.f;
#pragma unroll
        for (int j = 0; j < 8; j++) { float d = xv[j] - mean; s2 += d * d; }
#pragma unroll
        for (int o = 16; o > 0; o >>= 1) s2 += __shfl_xor_sync(0xffffffff, s2, o);
        const float rstd = rsqrtf(s2 * (1.f / EE) + LN_EPS);
        float4 gv0 = *(const float4*)&gamma[c0];
        float4 gv1 = *(const float4*)&gamma[c0 + 4];
        float4 bv0 = *(const float4*)&beta[c0];
        float4 bv1 = *(const float4*)&beta[c0 + 4];
        float y[8];
        y[0] = (xv[0] - mean) * rstd * gv0.x + bv0.x;
        y[1] = (xv[1] - mean) * rstd * gv0.y + bv0.y;
        y[2] = (xv[2] - mean) * rstd * gv0.z + bv0.z;
        y[3] = (xv[3] - mean) * rstd * gv0.w + bv0.w;
        y[4] = (xv[4] - mean) * rstd * gv1.x + bv1.x;
        y[5] = (xv[5] - mean) * rstd * gv1.y + bv1.y;
        y[6] = (xv[6] - mean) * rstd * gv1.z + bv1.z;
        y[7] = (xv[7] - mean) * rstd * gv1.w + bv1.w;
        *(float4*)&out[(size_t)gr * EE + c0]     = make_float4(y[0], y[1], y[2], y[3]);
        *(float4*)&out[(size_t)gr * EE + c0 + 4] = make_float4(y[4], y[5], y[6], y[7]);
        if (out_h) {
            uint4 hv;
            *(__half2*)&hv.x = __floats2half2_rn(y[0], y[1]);
            *(__half2*)&hv.y = __floats2half2_rn(y[2], y[3]);
            *(__half2*)&hv.z = __floats2half2_rn(y[4], y[5]);
            *(__half2*)&hv.w = __floats2half2_rn(y[6], y[7]);
            *(uint4*)&out_h[(size_t)gr * EE + c0] = hv;
        }
    }
}

// ---------------------------------------------------------------------------
// Fused fp32->fp16 for inputs + all weights (one launch)
// ---------------------------------------------------------------------------
#define N2_IN   (BB * SS * FIN / 2)
#define N2_EW   (EE * FIN / 2)
#define N2_QW   (2 * TE * EE / 2)
#define N2_AW   (2 * EE * EE / 2)
#define N2_F1W  (2 * FF * EE / 2)
#define N2_F2W  (2 * EE * FF / 2)
#define O_EW   (N2_IN)
#define O_QW   (O_EW + N2_EW)
#define O_AW   (O_QW + N2_QW)
#define O_F1W  (O_AW + N2_AW)
#define O_F2W  (O_F1W + N2_F1W)
#define N2_TOT (O_F2W + N2_F2W)

__global__ void f2h_all_kernel(const float2* __restrict__ in,
                               const float2* __restrict__ ew,
                               const float2* __restrict__ qw,
                               const float2* __restrict__ aw,
                               const float2* __restrict__ f1w,
                               const float2* __restrict__ f2w) {
    int i = blockIdx.x * blockDim.x + threadIdx.x;
    if (i >= N2_TOT) return;
    const float2* src;
    __half2* dst;
    int o;
    if (i < O_EW)        { src = in;  dst = (__half2*)g_in_h;  o = i; }
    else if (i < O_QW)   { src = ew;  dst = (__half2*)g_ew_h;  o = i - O_EW; }
    else if (i < O_AW)   { src = qw;  dst = (__half2*)g_qw_h;  o = i - O_QW; }
    else if (i < O_F1W)  { src = aw;  dst = (__half2*)g_aw_h;  o = i - O_AW; }
    else if (i < O_F2W)  { src = f1w; dst = (__half2*)g_f1w_h; o = i - O_F1W; }
    else                 { src = f2w; dst = (__half2*)g_f2w_h; o = i - O_F2W; }
    float2 v = src[o];
    dst[o] = __floats2half2_rn(v.x, v.y);
}

// ---------------------------------------------------------------------------
// Zero pad rows of g_emb / g_emb_h
// ---------------------------------------------------------------------------
__global__ void zero_pad_kernel() {
    int idx = blockIdx.x * blockDim.x + threadIdx.x;
    if (idx >= BB * (WW - 1) * EE) return;
    int e = idx & (EE - 1);
    int p = (idx >> 8) % (WW - 1);
    int b = idx / ((WW - 1) * EE);
    size_t o = ((size_t)b * PP + p) * EE + e;
    g_emb[o] = 0.f;
    g_emb_h[o] = __float2half(0.f);
}

// ---------------------------------------------------------------------------
// Layer-1 attention, full fp16 MMA. One block (128 thr, 4 warps) per (n,h).
// ---------------------------------------------------------------------------
#define QS(r, c) s_q[(r) * 40 + (c)]
#define KS(r, c) s_k[(r) * 40 + (c)]
#define VT(d, c) s_vt[(d) * 72 + (c)]
#define SC(r, c) s_s[(r) * 66 + (c)]
#define PS(r, c) s_p[(r) * 72 + (c)]

__global__ __launch_bounds__(128) void attn1_kernel(const __half* __restrict__ qkv,
                                                    __half* __restrict__ out_h) {
    __shared__ __half s_q[WW * 40], s_k[WW * 40];
    __shared__ __half s_vt[HD * 72];
    __shared__ float  s_s[WW * 66];
    __shared__ __half s_p[WW * 72];
    const int h = blockIdx.x;
    const int n = blockIdx.y;
    const int b = n >> 10, s = n & (SS - 1);
    const int tid = threadIdx.x;
    const int lane = tid & 31, w = tid >> 5;
    const int g = lane >> 2, t4 = lane & 3;

    size_t base = ((size_t)b * PP + s) * TE + h * HD;
    for (int t = tid; t < WW * HD / 2; t += 128) {
        int wpos = t >> 4, wd = (t & 15) * 2;
        size_t r = base + (size_t)wpos * TE + wd;
        __half2 qv = *(const __half2*)&qkv[r];
        __half2 kv = *(const __half2*)&qkv[r + EE];
        __half2 vv = *(const __half2*)&qkv[r + 2 * EE];
        *(__half2*)&QS(wpos, wd) = qv;
        *(__half2*)&KS(wpos, wd) = kv;
        VT(wd, wpos) = vv.x;
        VT(wd + 1, wpos) = vv.y;
    }
    __syncthreads();

    {
        float sacc[8][4];
#pragma unroll
        for (int i = 0; i < 8; i++)
#pragma unroll
            for (int j = 0; j < 4; j++) sacc[i][j] = 0.f;
#pragma unroll
        for (int k0 = 0; k0 < HD; k0 += 16) {
            uint32_t a[4];
            a[0] = *(const uint32_t*)&QS(16 * w + g, k0 + 2 * t4);
            a[1] = *(const uint32_t*)&QS(16 * w + g + 8, k0 + 2 * t4);
            a[2] = *(const uint32_t*)&QS(16 * w + g, k0 + 8 + 2 * t4);
            a[3] = *(const uint32_t*)&QS(16 * w + g + 8, k0 + 8 + 2 * t4);
#pragma unroll
            for (int nt = 0; nt < 8; nt++) {
                uint32_t bfr[2];
                bfr[0] = *(const uint32_t*)&KS(nt * 8 + g, k0 + 2 * t4);
                bfr[1] = *(const uint32_t*)&KS(nt * 8 + g, k0 + 8 + 2 * t4);
                mma_f16(sacc[nt], a, bfr);
            }
        }
#pragma unroll
        for (int nt = 0; nt < 8; nt++) {
            const int r0 = 16 * w + g, c = nt * 8 + 2 * t4;
            *(float2*)&SC(r0, c)     = make_float2(sacc[nt][0] * ATT_SCALE, sacc[nt][1] * ATT_SCALE);
            *(float2*)&SC(r0 + 8, c) = make_float2(sacc[nt][2] * ATT_SCALE, sacc[nt][3] * ATT_SCALE);
        }
    }
    __syncthreads();

    {
        const int row = tid >> 1, half_ = tid & 1;
        const int cb = half_ * 32;
        float mx = -1e30f;
#pragma unroll
        for (int j = 0; j < 32; j++) mx = fmaxf(mx, SC(row, cb + j));
        mx = fmaxf(mx, __shfl_xor_sync(0xffffffff, mx, 1));
        float ebuf[32];
        float sum = 0.f;
#pragma unroll
        for (int j = 0; j < 32; j++) {
            ebuf[j] = __expf(SC(row, cb + j) - mx);
            sum += ebuf[j];
        }
        sum += __shfl_xor_sync(0xffffffff, sum, 1);
        float inv = 1.f / sum;
#pragma unroll
        for (int j = 0; j < 32; j++)
            PS(row, cb + j) = __float2half(ebuf[j] * inv);
    }
    __syncthreads();

    {
        float oacc[4][4];
#pragma unroll
        for (int i = 0; i < 4; i++)
#pragma unroll
            for (int j = 0; j < 4; j++) oacc[i][j] = 0.f;
#pragma unroll
        for (int k0 = 0; k0 < WW; k0 += 16) {
            uint32_t a[4];
            a[0] = *(const uint32_t*)&PS(16 * w + g, k0 + 2 * t4);
            a[1] = *(const uint32_t*)&PS(16 * w + g + 8, k0 + 2 * t4);
            a[2] = *(const uint32_t*)&PS(16 * w + g, k0 + 8 + 2 * t4);
            a[3] = *(const uint32_t*)&PS(16 * w + g + 8, k0 + 8 + 2 * t4);
#pragma unroll
            for (int nt = 0; nt < 4; nt++) {
                uint32_t bfr[2];
                bfr[0] = *(const uint32_t*)&VT(nt * 8 + g, k0 + 2 * t4);
                bfr[1] = *(const uint32_t*)&VT(nt * 8 + g, k0 + 8 + 2 * t4);
                mma_f16(oacc[nt], a, bfr);
            }
        }
        const size_t row0 = ((size_t)n * WW + 16 * w + g) * EE + h * HD;
        const size_t row1 = row0 + 8 * EE;
#pragma unroll
        for (int nt = 0; nt < 4; nt++) {
            const int c = nt * 8 + 2 * t4;
            *(__half2*)&out_h[row0 + c] = __floats2half2_rn(oacc[nt][0], oacc[nt][1]);
            *(__half2*)&out_h[row1 + c] = __floats2half2_rn(oacc[nt][2], oacc[nt][3]);
        }
    }
}

// ---------------------------------------------------------------------------
// Layer-2 attention (pruned): Q fp32 [2048,256], KV fp16 [NROW,512] -> fp16
// ---------------------------------------------------------------------------
__global__ __launch_bounds__(64) void attn2_kernel(const float* __restrict__ q2,
                                                   const __half* __restrict__ kv,
                                                   __half* __restrict__ out_h) {
    int h = blockIdx.x;
    int n = blockIdx.y;
    int tid = threadIdx.x;
    __shared__ float ks[WW][HD + 1], vs[WW][HD + 1];
    __shared__ float q[HD], p[WW];

    size_t base = (size_t)n * WW * 512 + h * HD;
    for (int t = tid; t < WW * HD; t += 64) {
        int wpos = t >> 5, d = t & 31;
        size_t r = base + (size_t)wpos * 512 + d;
        ks[wpos][d] = __half2float(kv[r]);
        vs[wpos][d] = __half2float(kv[r + 256]);
    }
    if (tid < HD) q[tid] = q2[(size_t)n * EE + h * HD + tid];
    __syncthreads();

    {
        float dsum = 0.f;
#pragma unroll
        for (int d = 0; d < HD; d++) dsum = fmaf(q[d], ks[tid][d], dsum);
        p[tid] = dsum * ATT_SCALE;
    }
    __syncthreads();
    if (tid < 32) {
        float v = fmaxf(p[tid], p[tid + 32]);
#pragma unroll
        for (int o = 16; o > 0; o >>= 1) v = fmaxf(v, __shfl_xor_sync(0xffffffff, v, o));
        float e0 = __expf(p[tid] - v), e1 = __expf(p[tid + 32] - v);
        float sm = e0 + e1;
#pragma unroll
        for (int o = 16; o > 0; o >>= 1) sm += __shfl_xor_sync(0xffffffff, sm, o);
        float inv = 1.f / sm;
        p[tid] = e0 * inv; p[tid + 32] = e1 * inv;
    }
    __syncthreads();
    if (tid < HD) {
        float acc = 0.f;
#pragma unroll
        for (int j = 0; j < WW; j++) acc = fmaf(p[j], vs[j][tid], acc);
        out_h[(size_t)n * EE + h * HD + tid] = __float2half(acc);
    }
}

// ---------------------------------------------------------------------------
// Gather last window rows -> fp32 + fp16
// ---------------------------------------------------------------------------
__global__ void gather_last_kernel(const float* __restrict__ x2,
                                   float* __restrict__ xlast,
                                   __half* __restrict__ xlast_h) {
    int idx = blockIdx.x * blockDim.x + threadIdx.x;
    if (idx >= NWIN * EE) return;
    int n = idx >> 8, e = idx & 255;
    float v = x2[((size_t)n * WW + (WW - 1)) * EE + e];
    xlast[idx] = v;
    xlast_h[idx] = __float2half(v);
}

// ---------------------------------------------------------------------------
// Head
// ---------------------------------------------------------------------------
__global__ void head_kernel(const float* __restrict__ y,
                            const float* __restrict__ hw,
                            const float* __restrict__ hb,
                            float* __restrict__ out) {
    int idx = blockIdx.x * blockDim.x + threadIdx.x;
    if (idx >= NWIN * OUTD) return;
    int n = idx / OUTD, o = idx % OUTD;
    const float* yr = y + (size_t)n * EE;
    const float* wr = hw + (size_t)o * EE;
    float acc = hb[o];
#pragma unroll 8
    for (int k = 0; k < EE; k++) acc = fmaf(yr[k], wr[k], acc);
    out[idx] = acc;
}

// ---------------------------------------------------------------------------
// Host launch
// ---------------------------------------------------------------------------
static inline dim3 tgrid(int M, int N) {
    return dim3(N / 128, (M + 127) / 128);
}

extern "C" void kernel_launch(void* const* d_in, const int* in_sizes, int n_in,
                              void* d_out, int out_size) {
    const float* inputs     = (const float*)d_in[0];
    const float* embed_w    = (const float*)d_in[1];
    const float* embed_b    = (const float*)d_in[2];
    const float* qkv_w      = (const float*)d_in[3];
    const float* qkv_b      = (const float*)d_in[4];
    const float* attn_out_w = (const float*)d_in[5];
    const float* attn_out_b = (const float*)d_in[6];
    const float* ln1_g      = (const float*)d_in[7];
    const float* ln1_b      = (const float*)d_in[8];
    const float* ffn1_w     = (const float*)d_in[9];
    const float* ffn1_b     = (const float*)d_in[10];
    const float* ffn2_w     = (const float*)d_in[11];
    const float* ffn2_b     = (const float*)d_in[12];
    const float* ln2_g      = (const float*)d_in[13];
    const float* ln2_b      = (const float*)d_in[14];
    const float* head_w     = (const float*)d_in[15];
    const float* head_b     = (const float*)d_in[16];
    float* out = (float*)d_out;

    cudaFuncSetAttribute(tgemm_ln, cudaFuncAttributeMaxDynamicSharedMemorySize, F_SMEM_BYTES);

    float *emb, *bufA, *xlast, *r1, *r2;
    __half *ew_h, *qw_h, *aw_h, *f1w_h, *f2w_h, *in_h;
    __half *emb_h, *qkv_h, *attn_h, *x_h, *ffh_h, *kv2_h, *xlast_h, *r1_h, *r3_h;
    cudaGetSymbolAddress((void**)&emb,   g_emb);
    cudaGetSymbolAddress((void**)&bufA,  g_bufA);
    cudaGetSymbolAddress((void**)&xlast, g_xlast);
    cudaGetSymbolAddress((void**)&r1,    g_r1);
    cudaGetSymbolAddress((void**)&r2,    g_r2);
    cudaGetSymbolAddress((void**)&in_h,   g_in_h);
    cudaGetSymbolAddress((void**)&ew_h,   g_ew_h);
    cudaGetSymbolAddress((void**)&qw_h,   g_qw_h);
    cudaGetSymbolAddress((void**)&aw_h,   g_aw_h);
    cudaGetSymbolAddress((void**)&f1w_h,  g_f1w_h);
    cudaGetSymbolAddress((void**)&f2w_h,  g_f2w_h);
    cudaGetSymbolAddress((void**)&emb_h,  g_emb_h);
    cudaGetSymbolAddress((void**)&qkv_h,  g_qkv_h);
    cudaGetSymbolAddress((void**)&attn_h, g_attn_h);
    cudaGetSymbolAddress((void**)&x_h,    g_x_h);
    cudaGetSymbolAddress((void**)&ffh_h,  g_ffh_h);
    cudaGetSymbolAddress((void**)&kv2_h,  g_kv2_h);
    cudaGetSymbolAddress((void**)&xlast_h, g_xlast_h);
    cudaGetSymbolAddress((void**)&r1_h,   g_r1_h);
    cudaGetSymbolAddress((void**)&r3_h,   g_r3_h);

    // 0. fused fp16 conversions + pad zeroing
    f2h_all_kernel<<<(N2_TOT + 255) / 256, 256>>>(
        (const float2*)inputs, (const float2*)embed_w, (const float2*)qkv_w,
        (const float2*)attn_out_w, (const float2*)ffn1_w, (const float2*)ffn2_w);
    zero_pad_kernel<<<(BB * (WW - 1) * EE + 255) / 256, 256>>>();

    // 1. embedding (per batch)
    for (int b = 0; b < BB; b++) {
        size_t off = ((size_t)b * PP + (WW - 1)) * EE;
        tgemm_h<<<tgrid(SS, EE), 256>>>(in_h + (size_t)b * SS * FIN, ew_h, embed_b,
                                        emb + off, emb_h + off,
                                        SS, EE, FIN, FIN, FIN, EE, 0);
    }
    // 2. Layer-1 QKV (shared) -> fp16
    tgemm_h<<<tgrid(BB * PP, TE), 256>>>(emb_h, qw_h, qkv_b, (float*)0, qkv_h,
                                         BB * PP, TE, EE, EE, EE, TE, 0);
    // 3. attention -> fp16
    attn1_kernel<<<dim3(NH, NWIN), 128>>>(qkv_h, attn_h);
    // 4+5. proj + LN1 fused -> bufA + x_h
    tgemm_ln<<<NROW / 128, 256, F_SMEM_BYTES>>>(attn_h, aw_h, attn_out_b, emb,
                                                ln1_g, ln1_b, bufA, x_h,
                                                NROW, EE, EE, EE, 1);
    // 6. FFN hidden (silu) -> fp16
    tgemm_h<<<tgrid(NROW, FF), 256>>>(x_h, f1w_h, ffn1_b, (float*)0, ffh_h,
                                      NROW, FF, EE, EE, EE, FF, 1);
    // 7+8. FFN out + LN2 fused -> bufA + x_h (residual = bufA, in-place safe)
    tgemm_ln<<<NROW / 128, 256, F_SMEM_BYTES>>>(ffh_h, f2w_h, ffn2_b, bufA,
                                                ln2_g, ln2_b, bufA, x_h,
                                                NROW, FF, FF, FF, 0);

    // ---- Layer 2 (output pruned) ----
    // 9. gather last rows; Q only for last rows -> fp32 r2
    gather_last_kernel<<<(NWIN * EE + 255) / 256, 256>>>(bufA, xlast, xlast_h);
    tgemm_h<<<tgrid(NWIN, EE), 256>>>(xlast_h, qw_h + (size_t)TE * EE, qkv_b + TE,
                                      r2, (__half*)0, NWIN, EE, EE, EE, EE, EE, 0);
    // 10. KV for all rows -> fp16 kv2_h
    tgemm_h<<<tgrid(NROW, 512), 256>>>(x_h, qw_h + (size_t)TE * EE + (size_t)EE * EE,
                                       qkv_b + TE + EE, (float*)0, kv2_h,
                                       NROW, 512, EE, EE, EE, 512, 0);
    // 11. attention -> fp16 r1_h
    attn2_kernel<<<dim3(NH, NWIN), 64>>>(r2, kv2_h, r1_h);
    // 12+13. proj + LN1_l2 fused -> r1 + r1_h (A=r1_h safe: per-CTA rows only)
    tgemm_ln<<<NWIN / 128, 256, F_SMEM_BYTES>>>(r1_h, aw_h + (size_t)EE * EE,
                                                attn_out_b + EE, xlast,
                                                ln1_g + EE, ln1_b + EE, r1, r1_h,
                                                NWIN, EE, EE, EE, 0);
    // 14. h2 = silu(y @ W1^T) -> fp16 r3_h
    tgemm_h<<<tgrid(NWIN, FF), 256>>>(r1_h, f1w_h + (size_t)FF * EE, ffn1_b + FF,
                                      (float*)0, r3_h, NWIN, FF, EE, EE, EE, FF, 1);
    // 15+16. FFN out + LN2_l2 fused -> r1 (residual = r1, in-place safe)
    tgemm_ln<<<NWIN / 128, 256, F_SMEM_BYTES>>>(r3_h, f2w_h + (size_t)EE * FF,
                                                ffn2_b + EE, r1,
                                                ln2_g + EE, ln2_b + EE, r1, (__half*)0,
                                                NWIN, FF, FF, FF, 0);
    // 17. head -> d_out
    head_kernel<<<(NWIN * OUTD + 255) / 256, 256>>>(r1, head_w, head_b, out);
}

// round 16
// speedup vs baseline: 1.0833x; 1.0057x over previous
#include <cuda_runtime.h>
#include <cuda_fp16.h>
#include <math.h>
#include <stdint.h>

// ---------------------------------------------------------------------------
// Problem constants
// ---------------------------------------------------------------------------
#define BB 2
#define SS 1024
#define WW 64
#define PP (SS + WW - 1)   // 1087
#define EE 256
#define FIN 64
#define FF 1024
#define TE 768
#define NH 8
#define HD 32
#define NWIN (BB * SS)     // 2048
#define NROW (NWIN * WW)   // 131072
#define OUTD 10
#define LN_EPS 1e-5f
#define ATT_SCALE 0.17677669529663687f

// ---------------------------------------------------------------------------
// Scratch (fp32)
// ---------------------------------------------------------------------------
__device__ float g_emb  [BB * PP * EE];
__device__ float g_bufA [(size_t)NROW * EE];   // x1 / x2 (residual chain)
__device__ float g_r1   [NWIN * EE];
__device__ float g_r2   [NWIN * EE];

// Scratch (fp16)
__device__ __half g_in_h  [BB * SS * FIN];
__device__ __half g_ew_h  [EE * FIN];
__device__ __half g_qw_h  [2 * TE * EE];
__device__ __half g_aw_h  [2 * EE * EE];
__device__ __half g_f1w_h [2 * FF * EE];
__device__ __half g_f2w_h [2 * EE * FF];
__device__ __half g_emb_h [BB * PP * EE];
__device__ __half g_qkv_h [BB * PP * TE];
__device__ __half g_attn_h[(size_t)NROW * EE];
__device__ __half g_x_h   [(size_t)NROW * EE];
__device__ __half g_ffh_h [(size_t)NROW * FF];
__device__ __half g_kv2_h [(size_t)NROW * 512];
__device__ __half g_r1_h  [NWIN * EE];
__device__ __half g_r3_h  [NWIN * FF];

// ---------------------------------------------------------------------------
// MMA helpers
// ---------------------------------------------------------------------------
__device__ __forceinline__ void mma_f16(float* c, const uint32_t* a, const uint32_t* b) {
    asm volatile(
        "mma.sync.aligned.m16n8k16.row.col.f32.f16.f16.f32 "
        "{%0,%1,%2,%3},{%4,%5,%6,%7},{%8,%9},{%0,%1,%2,%3};"
        : "+f"(c[0]), "+f"(c[1]), "+f"(c[2]), "+f"(c[3])
        : "r"(a[0]), "r"(a[1]), "r"(a[2]), "r"(a[3]), "r"(b[0]), "r"(b[1]));
}

__device__ __forceinline__ void cp16(void* s, const void* g) {
    uint32_t sa = (uint32_t)__cvta_generic_to_shared(s);
    asm volatile("cp.async.cg.shared.global [%0], [%1], 16;" :: "r"(sa), "l"(g));
}

__device__ __forceinline__ void ldsm4(uint32_t* r, uint32_t addr) {
    asm volatile("ldmatrix.sync.aligned.m8n8.x4.shared.b16 {%0,%1,%2,%3}, [%4];"
        : "=r"(r[0]), "=r"(r[1]), "=r"(r[2]), "=r"(r[3]) : "r"(addr));
}

// embed row remap: logical row r -> padded row
__device__ __forceinline__ int emb_remap(int r) {
    return (r >> 10) * PP + (WW - 1) + (r & (SS - 1));
}

// ---------------------------------------------------------------------------
// FP16 tensor-core GEMM (NT): C = act(A[M,K] * B[N,K]^T + bias)  [R12 proven]
// 128x128 tile, BK=32, double-buffered cp.async with load/compute overlap.
// remap=1: output rows remapped into padded embedding layout.
// ---------------------------------------------------------------------------
#define HBK 32
#define HSM 40
#define HBUF (128 * HSM * 2)   // bytes per stage

__global__ __launch_bounds__(256, 2) void tgemm_h(
    const __half* __restrict__ A, const __half* __restrict__ B,
    const float* __restrict__ bias, float* __restrict__ Cf,
    __half* __restrict__ Ch,
    int M, int N, int K, int lda, int ldb, int ldc, int act, int remap) {
    __shared__ __align__(16) __half As[2][128][HSM];
    __shared__ __align__(16) __half Bs[2][128][HSM];
    const int tid = threadIdx.x;
    const int bm = blockIdx.y * 128, bn = blockIdx.x * 128;
    const int lane = tid & 31, wid = tid >> 5;
    const int wm = (wid >> 2) * 64, wn = (wid & 3) * 32;
    const int g = lane >> 2, t4 = lane & 3;
    const int quad = lane >> 3, r8 = lane & 7;
    const int a_row = (quad & 1) * 8 + r8, a_colq = (quad >> 1) * 8;
    const int b_row = (quad >> 1) * 8 + r8, b_colq = (quad & 1) * 8;
    const uint32_t sA = (uint32_t)__cvta_generic_to_shared(&As[0][0][0]);
    const uint32_t sB = (uint32_t)__cvta_generic_to_shared(&Bs[0][0][0]);

    float acc[4][4][4];
#pragma unroll
    for (int i = 0; i < 4; i++)
#pragma unroll
        for (int j = 0; j < 4; j++)
#pragma unroll
            for (int k = 0; k < 4; k++) acc[i][j][k] = 0.f;

    const int T = K / HBK;
    const int lr = tid >> 1, lh = (tid & 1) * 16;
    int ga = bm + lr; if (ga >= M) ga = M - 1;
    const int gb = bn + lr;

    cp16(&As[0][lr][lh],     A + (size_t)ga * lda + lh);
    cp16(&As[0][lr][lh + 8], A + (size_t)ga * lda + lh + 8);
    cp16(&Bs[0][lr][lh],     B + (size_t)gb * ldb + lh);
    cp16(&Bs[0][lr][lh + 8], B + (size_t)gb * ldb + lh + 8);
    asm volatile("cp.async.commit_group;");

    for (int t = 0; t < T; t++) {
        const int cur = t & 1;
        if (t + 1 < T) {
            const int k0 = (t + 1) * HBK;
            const int nxt = cur ^ 1;
            cp16(&As[nxt][lr][lh],     A + (size_t)ga * lda + k0 + lh);
            cp16(&As[nxt][lr][lh + 8], A + (size_t)ga * lda + k0 + lh + 8);
            cp16(&Bs[nxt][lr][lh],     B + (size_t)gb * ldb + k0 + lh);
            cp16(&Bs[nxt][lr][lh + 8], B + (size_t)gb * ldb + k0 + lh + 8);
            asm volatile("cp.async.commit_group;");
            asm volatile("cp.async.wait_group 1;");
        } else {
            asm volatile("cp.async.wait_group 0;");
        }
        __syncthreads();

        const uint32_t aBase = sA + cur * HBUF;
        const uint32_t bBase = sB + cur * HBUF;
#pragma unroll
        for (int ks = 0; ks < 2; ks++) {
            const int kc = ks * 16;
            uint32_t af[4][4], bf[4][2];
#pragma unroll
            for (int mt = 0; mt < 4; mt++)
                ldsm4(af[mt], aBase + ((wm + mt * 16 + a_row) * HSM + kc + a_colq) * 2);
#pragma unroll
            for (int ntp = 0; ntp < 2; ntp++) {
                uint32_t bt[4];
                ldsm4(bt, bBase + ((wn + ntp * 16 + b_row) * HSM + kc + b_colq) * 2);
                bf[2 * ntp][0] = bt[0]; bf[2 * ntp][1] = bt[1];
                bf[2 * ntp + 1][0] = bt[2]; bf[2 * ntp + 1][1] = bt[3];
            }
#pragma unroll
            for (int mt = 0; mt < 4; mt++)
#pragma unroll
                for (int nt = 0; nt < 4; nt++)
                    mma_f16(acc[mt][nt], af[mt], bf[nt]);
        }
        __syncthreads();
    }

#pragma unroll
    for (int mt = 0; mt < 4; mt++) {
        const int rA = bm + wm + mt * 16 + g;
        const int rB = rA + 8;
        const int oA = remap ? emb_remap(rA) : rA;
        const int oB = remap ? emb_remap(rB) : rB;
#pragma unroll
        for (int nt = 0; nt < 4; nt++) {
            const int c = bn + wn + nt * 8 + 2 * t4;
            const float b0 = bias ? bias[c] : 0.f;
            const float b1 = bias ? bias[c + 1] : 0.f;
            float v0 = acc[mt][nt][0] + b0, v1 = acc[mt][nt][1] + b1;
            float v2 = acc[mt][nt][2] + b0, v3 = acc[mt][nt][3] + b1;
            if (act == 1) {
                v0 = v0 / (1.f + __expf(-v0));
                v1 = v1 / (1.f + __expf(-v1));
                v2 = v2 / (1.f + __expf(-v2));
                v3 = v3 / (1.f + __expf(-v3));
            }
            if (rA < M) {
                if (Cf) *(float2*)&Cf[(size_t)oA * ldc + c] = make_float2(v0, v1);
                if (Ch) *(__half2*)&Ch[(size_t)oA * ldc + c] = __floats2half2_rn(v0, v1);
            }
            if (rB < M) {
                if (Cf) *(float2*)&Cf[(size_t)oB * ldc + c] = make_float2(v2, v3);
                if (Ch) *(__half2*)&Ch[(size_t)oB * ldc + c] = __floats2half2_rn(v2, v3);
            }
        }
    }
}

// ---------------------------------------------------------------------------
// Fused GEMM (NT, N=256 full width) + bias + residual-add + LayerNorm.
// mode 0: residual row = global row; mode 1: residual = g_emb window view;
// mode 2: residual = res[(gr*WW + WW-1)*EE] (layer-2 last-row view of bufA).
// ---------------------------------------------------------------------------
#define FSM 40
#define F_ASTG (128 * FSM)
#define F_BSTG (256 * FSM)
#define F_CSM 264
#define F_SMEM_BYTES (128 * F_CSM * 2 > 2 * (F_ASTG + F_BSTG) * 2 ? 128 * F_CSM * 2 : 2 * (F_ASTG + F_BSTG) * 2)

extern __shared__ __half fsm_[];

__global__ __launch_bounds__(256, 1) void tgemm_ln(
    const __half* __restrict__ A, const __half* __restrict__ B,
    const float* __restrict__ bias, const float* __restrict__ res,
    const float* __restrict__ gamma, const float* __restrict__ beta,
    float* __restrict__ out, __half* __restrict__ out_h,
    int M, int K, int lda, int ldb, int mode) {
    __half* Asm = fsm_;
    __half* Bsm = fsm_ + 2 * F_ASTG;
    __half* Csm = fsm_;
    const int tid = threadIdx.x;
    const int bm = blockIdx.x * 128;
    const int lane = tid & 31, wid = tid >> 5;
    const int wm = (wid >> 2) * 64, wnb = (wid & 3) * 32;
    const int g = lane >> 2, t4 = lane & 3;
    const int quad = lane >> 3, r8 = lane & 7;
    const int a_row = (quad & 1) * 8 + r8, a_colq = (quad >> 1) * 8;
    const int b_row = (quad >> 1) * 8 + r8, b_colq = (quad & 1) * 8;
    const uint32_t sA = (uint32_t)__cvta_generic_to_shared(Asm);
    const uint32_t sB = (uint32_t)__cvta_generic_to_shared(Bsm);

    float acc[2][4][4][4];
#pragma unroll
    for (int hh = 0; hh < 2; hh++)
#pragma unroll
        for (int i = 0; i < 4; i++)
#pragma unroll
            for (int j = 0; j < 4; j++)
#pragma unroll
                for (int k = 0; k < 4; k++) acc[hh][i][j][k] = 0.f;

    const int T = K / HBK;
    const int lr = tid >> 1, lh = (tid & 1) * 16;
    int ga = bm + lr; if (ga >= M) ga = M - 1;

    cp16(&Asm[lr * FSM + lh],     A + (size_t)ga * lda + lh);
    cp16(&Asm[lr * FSM + lh + 8], A + (size_t)ga * lda + lh + 8);
#pragma unroll
    for (int o = 0; o < 32; o += 8)
        cp16(&Bsm[tid * FSM + o], B + (size_t)tid * ldb + o);
    asm volatile("cp.async.commit_group;");

    for (int t = 0; t < T; t++) {
        const int cur = t & 1;
        if (t + 1 < T) {
            const int k0 = (t + 1) * HBK;
            const int nxt = cur ^ 1;
            cp16(&Asm[nxt * F_ASTG + lr * FSM + lh],     A + (size_t)ga * lda + k0 + lh);
            cp16(&Asm[nxt * F_ASTG + lr * FSM + lh + 8], A + (size_t)ga * lda + k0 + lh + 8);
#pragma unroll
            for (int o = 0; o < 32; o += 8)
                cp16(&Bsm[nxt * F_BSTG + tid * FSM + o], B + (size_t)tid * ldb + k0 + o);
            asm volatile("cp.async.commit_group;");
            asm volatile("cp.async.wait_group 1;");
        } else {
            asm volatile("cp.async.wait_group 0;");
        }
        __syncthreads();

        const uint32_t aBase = sA + cur * (F_ASTG * 2);
        const uint32_t bBase = sB + cur * (F_BSTG * 2);
#pragma unroll
        for (int ks = 0; ks < 2; ks++) {
            const int kc = ks * 16;
            uint32_t af[4][4];
#pragma unroll
            for (int mt = 0; mt < 4; mt++)
                ldsm4(af[mt], aBase + ((wm + mt * 16 + a_row) * FSM + kc + a_colq) * 2);
#pragma unroll
            for (int hh = 0; hh < 2; hh++) {
                const int col0 = hh * 128 + wnb;
                uint32_t bf[4][2];
#pragma unroll
                for (int ntp = 0; ntp < 2; ntp++) {
                    uint32_t bt[4];
                    ldsm4(bt, bBase + ((col0 + ntp * 16 + b_row) * FSM + kc + b_colq) * 2);
                    bf[2 * ntp][0] = bt[0]; bf[2 * ntp][1] = bt[1];
                    bf[2 * ntp + 1][0] = bt[2]; bf[2 * ntp + 1][1] = bt[3];
                }
#pragma unroll
                for (int mt = 0; mt < 4; mt++)
#pragma unroll
                    for (int nt = 0; nt < 4; nt++)
                        mma_f16(acc[hh][mt][nt], af[mt], bf[nt]);
            }
        }
        __syncthreads();
    }

#pragma unroll
    for (int hh = 0; hh < 2; hh++)
#pragma unroll
        for (int mt = 0; mt < 4; mt++) {
            const int r0 = wm + mt * 16 + g;
#pragma unroll
            for (int nt = 0; nt < 4; nt++) {
                const int c = hh * 128 + wnb + nt * 8 + 2 * t4;
                const float b0 = bias[c], b1 = bias[c + 1];
                *(__half2*)&Csm[r0 * F_CSM + c] =
                    __floats2half2_rn(acc[hh][mt][nt][0] + b0, acc[hh][mt][nt][1] + b1);
                *(__half2*)&Csm[(r0 + 8) * F_CSM + c] =
                    __floats2half2_rn(acc[hh][mt][nt][2] + b0, acc[hh][mt][nt][3] + b1);
            }
        }
    __syncthreads();

    const int c0 = lane * 8;
    for (int i = 0; i < 16; i++) {
        const int row = wid * 16 + i;
        const int gr = bm + row;
        if (gr >= M) break;
        size_t roff;
        if (mode == 0) roff = (size_t)gr * EE;
        else if (mode == 1) {
            int n = gr >> 6, wp = gr & 63;
            int b = n >> 10, s = n & (SS - 1);
            roff = ((size_t)b * PP + s + wp) * EE;
        } else {
            roff = ((size_t)gr * WW + (WW - 1)) * EE;
        }
        uint4 cv = *(uint4*)&Csm[row * F_CSM + c0];
        __half2 ch[4];
        ch[0] = *(__half2*)&cv.x; ch[1] = *(__half2*)&cv.y;
        ch[2] = *(__half2*)&cv.z; ch[3] = *(__half2*)&cv.w;
        float4 rv0 = *(const float4*)&res[roff + c0];
        float4 rv1 = *(const float4*)&res[roff + c0 + 4];
        float xv[8];
        xv[0] = __half2float(ch[0].x) + rv0.x; xv[1] = __half2float(ch[0].y) + rv0.y;
        xv[2] = __half2float(ch[1].x) + rv0.z; xv[3] = __half2float(ch[1].y) + rv0.w;
        xv[4] = __half2float(ch[2].x) + rv1.x; xv[5] = __half2float(ch[2].y) + rv1.y;
        xv[6] = __half2float(ch[3].x) + rv1.z; xv[7] = __half2float(ch[3].y) + rv1.w;
        float s1 = 0.f;
#pragma unroll
        for (int j = 0; j < 8; j++) s1 += xv[j];
#pragma unroll
        for (int o = 16; o > 0; o >>= 1) s1 += __shfl_xor_sync(0xffffffff, s1, o);
        const float mean = s1 * (1.f / EE);
        float s2 = 0.f;
#pragma unroll
        for (int j = 0; j < 8; j++) { float d = xv[j] - mean; s2 += d * d; }
#pragma unroll
        for (int o = 16; o > 0; o >>= 1) s2 += __shfl_xor_sync(0xffffffff, s2, o);
        const float rstd = rsqrtf(s2 * (1.f / EE) + LN_EPS);
        float4 gv0 = *(const float4*)&gamma[c0];
        float4 gv1 = *(const float4*)&gamma[c0 + 4];
        float4 bv0 = *(const float4*)&beta[c0];
        float4 bv1 = *(const float4*)&beta[c0 + 4];
        float y[8];
        y[0] = (xv[0] - mean) * rstd * gv0.x + bv0.x;
        y[1] = (xv[1] - mean) * rstd * gv0.y + bv0.y;
        y[2] = (xv[2] - mean) * rstd * gv0.z + bv0.z;
        y[3] = (xv[3] - mean) * rstd * gv0.w + bv0.w;
        y[4] = (xv[4] - mean) * rstd * gv1.x + bv1.x;
        y[5] = (xv[5] - mean) * rstd * gv1.y + bv1.y;
        y[6] = (xv[6] - mean) * rstd * gv1.z + bv1.z;
        y[7] = (xv[7] - mean) * rstd * gv1.w + bv1.w;
        *(float4*)&out[(size_t)gr * EE + c0]     = make_float4(y[0], y[1], y[2], y[3]);
        *(float4*)&out[(size_t)gr * EE + c0 + 4] = make_float4(y[4], y[5], y[6], y[7]);
        if (out_h) {
            uint4 hv;
            *(__half2*)&hv.x = __floats2half2_rn(y[0], y[1]);
            *(__half2*)&hv.y = __floats2half2_rn(y[2], y[3]);
            *(__half2*)&hv.z = __floats2half2_rn(y[4], y[5]);
            *(__half2*)&hv.w = __floats2half2_rn(y[6], y[7]);
            *(uint4*)&out_h[(size_t)gr * EE + c0] = hv;
        }
    }
}

// ---------------------------------------------------------------------------
// Fused fp32->fp16 for inputs + all weights + embedding pad zeroing (1 launch)
// ---------------------------------------------------------------------------
#define N2_IN   (BB * SS * FIN / 2)
#define N2_EW   (EE * FIN / 2)
#define N2_QW   (2 * TE * EE / 2)
#define N2_AW   (2 * EE * EE / 2)
#define N2_F1W  (2 * FF * EE / 2)
#define N2_F2W  (2 * EE * FF / 2)
#define N2_PAD  (BB * (WW - 1) * EE / 2)
#define O_EW   (N2_IN)
#define O_QW   (O_EW + N2_EW)
#define O_AW   (O_QW + N2_QW)
#define O_F1W  (O_AW + N2_AW)
#define O_F2W  (O_F1W + N2_F1W)
#define O_PAD  (O_F2W + N2_F2W)
#define N2_TOT (O_PAD + N2_PAD)

__global__ void f2h_all_kernel(const float2* __restrict__ in,
                               const float2* __restrict__ ew,
                               const float2* __restrict__ qw,
                               const float2* __restrict__ aw,
                               const float2* __restrict__ f1w,
                               const float2* __restrict__ f2w) {
    int i = blockIdx.x * blockDim.x + threadIdx.x;
    if (i >= N2_TOT) return;
    if (i >= O_PAD) {
        int p2 = i - O_PAD;               // pair index in pad region
        int e2 = p2 & (EE / 2 - 1);       // pair within row
        int pr = p2 / (EE / 2);           // pad row: b*(WW-1)+p
        int b = pr / (WW - 1), p = pr % (WW - 1);
        size_t o = ((size_t)b * PP + p) * EE + e2 * 2;
        *(float2*)&g_emb[o] = make_float2(0.f, 0.f);
        *(__half2*)&g_emb_h[o] = __floats2half2_rn(0.f, 0.f);
        return;
    }
    const float2* src;
    __half2* dst;
    int o;
    if (i < O_EW)        { src = in;  dst = (__half2*)g_in_h;  o = i; }
    else if (i < O_QW)   { src = ew;  dst = (__half2*)g_ew_h;  o = i - O_EW; }
    else if (i < O_AW)   { src = qw;  dst = (__half2*)g_qw_h;  o = i - O_QW; }
    else if (i < O_F1W)  { src = aw;  dst = (__half2*)g_aw_h;  o = i - O_AW; }
    else if (i < O_F2W)  { src = f1w; dst = (__half2*)g_f1w_h; o = i - O_F1W; }
    else                 { src = f2w; dst = (__half2*)g_f2w_h; o = i - O_F2W; }
    float2 v = src[o];
    dst[o] = __floats2half2_rn(v.x, v.y);
}

// ---------------------------------------------------------------------------
// Layer-1 attention, full fp16 MMA. One block (128 thr, 4 warps) per (n,h).
// ---------------------------------------------------------------------------
#define QS(r, c) s_q[(r) * 40 + (c)]
#define KS(r, c) s_k[(r) * 40 + (c)]
#define VT(d, c) s_vt[(d) * 72 + (c)]
#define SC(r, c) s_s[(r) * 66 + (c)]
#define PS(r, c) s_p[(r) * 72 + (c)]

__global__ __launch_bounds__(128) void attn1_kernel(const __half* __restrict__ qkv,
                                                    __half* __restrict__ out_h) {
    __shared__ __half s_q[WW * 40], s_k[WW * 40];
    __shared__ __half s_vt[HD * 72];
    __shared__ float  s_s[WW * 66];
    __shared__ __half s_p[WW * 72];
    const int h = blockIdx.x;
    const int n = blockIdx.y;
    const int b = n >> 10, s = n & (SS - 1);
    const int tid = threadIdx.x;
    const int lane = tid & 31, w = tid >> 5;
    const int g = lane >> 2, t4 = lane & 3;

    size_t base = ((size_t)b * PP + s) * TE + h * HD;
    for (int t = tid; t < WW * HD / 2; t += 128) {
        int wpos = t >> 4, wd = (t & 15) * 2;
        size_t r = base + (size_t)wpos * TE + wd;
        __half2 qv = *(const __half2*)&qkv[r];
        __half2 kv = *(const __half2*)&qkv[r + EE];
        __half2 vv = *(const __half2*)&qkv[r + 2 * EE];
        *(__half2*)&QS(wpos, wd) = qv;
        *(__half2*)&KS(wpos, wd) = kv;
        VT(wd, wpos) = vv.x;
        VT(wd + 1, wpos) = vv.y;
    }
    __syncthreads();

    {
        float sacc[8][4];
#pragma unroll
        for (int i = 0; i < 8; i++)
#pragma unroll
            for (int j = 0; j < 4; j++) sacc[i][j] = 0.f;
#pragma unroll
        for (int k0 = 0; k0 < HD; k0 += 16) {
            uint32_t a[4];
            a[0] = *(const uint32_t*)&QS(16 * w + g, k0 + 2 * t4);
            a[1] = *(const uint32_t*)&QS(16 * w + g + 8, k0 + 2 * t4);
            a[2] = *(const uint32_t*)&QS(16 * w + g, k0 + 8 + 2 * t4);
            a[3] = *(const uint32_t*)&QS(16 * w + g + 8, k0 + 8 + 2 * t4);
#pragma unroll
            for (int nt = 0; nt < 8; nt++) {
                uint32_t bfr[2];
                bfr[0] = *(const uint32_t*)&KS(nt * 8 + g, k0 + 2 * t4);
                bfr[1] = *(const uint32_t*)&KS(nt * 8 + g, k0 + 8 + 2 * t4);
                mma_f16(sacc[nt], a, bfr);
            }
        }
#pragma unroll
        for (int nt = 0; nt < 8; nt++) {
            const int r0 = 16 * w + g, c = nt * 8 + 2 * t4;
            *(float2*)&SC(r0, c)     = make_float2(sacc[nt][0] * ATT_SCALE, sacc[nt][1] * ATT_SCALE);
            *(float2*)&SC(r0 + 8, c) = make_float2(sacc[nt][2] * ATT_SCALE, sacc[nt][3] * ATT_SCALE);
        }
    }
    __syncthreads();

    {
        const int row = tid >> 1, half_ = tid & 1;
        const int cb = half_ * 32;
        float mx = -1e30f;
#pragma unroll
        for (int j = 0; j < 32; j++) mx = fmaxf(mx, SC(row, cb + j));
        mx = fmaxf(mx, __shfl_xor_sync(0xffffffff, mx, 1));
        float ebuf[32];
        float sum = 0.f;
#pragma unroll
        for (int j = 0; j < 32; j++) {
            ebuf[j] = __expf(SC(row, cb + j) - mx);
            sum += ebuf[j];
        }
        sum += __shfl_xor_sync(0xffffffff, sum, 1);
        float inv = 1.f / sum;
#pragma unroll
        for (int j = 0; j < 32; j++)
            PS(row, cb + j) = __float2half(ebuf[j] * inv);
    }
    __syncthreads();

    {
        float oacc[4][4];
#pragma unroll
        for (int i = 0; i < 4; i++)
#pragma unroll
            for (int j = 0; j < 4; j++) oacc[i][j] = 0.f;
#pragma unroll
        for (int k0 = 0; k0 < WW; k0 += 16) {
            uint32_t a[4];
            a[0] = *(const uint32_t*)&PS(16 * w + g, k0 + 2 * t4);
            a[1] = *(const uint32_t*)&PS(16 * w + g + 8, k0 + 2 * t4);
            a[2] = *(const uint32_t*)&PS(16 * w + g, k0 + 8 + 2 * t4);
            a[3] = *(const uint32_t*)&PS(16 * w + g + 8, k0 + 8 + 2 * t4);
#pragma unroll
            for (int nt = 0; nt < 4; nt++) {
                uint32_t bfr[2];
                bfr[0] = *(const uint32_t*)&VT(nt * 8 + g, k0 + 2 * t4);
                bfr[1] = *(const uint32_t*)&VT(nt * 8 + g, k0 + 8 + 2 * t4);
                mma_f16(oacc[nt], a, bfr);
            }
        }
        const size_t row0 = ((size_t)n * WW + 16 * w + g) * EE + h * HD;
        const size_t row1 = row0 + 8 * EE;
#pragma unroll
        for (int nt = 0; nt < 4; nt++) {
            const int c = nt * 8 + 2 * t4;
            *(__half2*)&out_h[row0 + c] = __floats2half2_rn(oacc[nt][0], oacc[nt][1]);
            *(__half2*)&out_h[row1 + c] = __floats2half2_rn(oacc[nt][2], oacc[nt][3]);
        }
    }
}

// ---------------------------------------------------------------------------
// Layer-2 attention (pruned), one block per WINDOW (256 thr, all 8 heads).
// KV smem stride 514 halves -> conflict-free K-dot and V-accumulate.
// ---------------------------------------------------------------------------
#define A2_KVS 514
#define A2_SMEM (WW * A2_KVS * 2 + EE * 4 + NH * 72 * 4)

extern __shared__ char a2sm_[];

__global__ __launch_bounds__(256) void attn2_kernel(const float* __restrict__ q2,
                                                    const __half* __restrict__ kv,
                                                    __half* __restrict__ out_h) {
    __half* kvs = (__half*)a2sm_;                        // [64][514]
    float* qs   = (float*)(a2sm_ + WW * A2_KVS * 2);     // [256]
    float* sc   = qs + EE;                               // [8][72]
    const int n = blockIdx.x;
    const int tid = threadIdx.x;
    const int lane = tid & 31, w = tid >> 5;

    // coalesced KV load: 64 rows x 512 halves
    const __half* src = kv + (size_t)n * WW * 512;
    for (int t = tid; t < WW * 64; t += 256) {
        int row = t >> 6, c = t & 63;
        uint4 v = *(const uint4*)(src + (size_t)row * 512 + c * 8);
        __half* d = kvs + row * A2_KVS + c * 8;
        *(uint32_t*)(d + 0) = v.x;
        *(uint32_t*)(d + 2) = v.y;
        *(uint32_t*)(d + 4) = v.z;
        *(uint32_t*)(d + 6) = v.w;
    }
    qs[tid] = q2[(size_t)n * EE + tid];
    __syncthreads();

    // scores: 512 tasks (h,j), 2 per thread
    for (int t = tid; t < NH * WW; t += 256) {
        int j = t & 63, h = t >> 6;
        const __half* kr = kvs + j * A2_KVS + h * HD;
        const float* qh = qs + h * HD;
        float dsum = 0.f;
#pragma unroll
        for (int d = 0; d < HD; d++) dsum = fmaf(__half2float(kr[d]), qh[d], dsum);
        sc[h * 72 + j] = dsum * ATT_SCALE;
    }
    __syncthreads();

    // softmax: warp w handles head w
    {
        float v0 = sc[w * 72 + lane], v1 = sc[w * 72 + lane + 32];
        float mx = fmaxf(v0, v1);
#pragma unroll
        for (int o = 16; o > 0; o >>= 1) mx = fmaxf(mx, __shfl_xor_sync(0xffffffff, mx, o));
        float e0 = __expf(v0 - mx), e1 = __expf(v1 - mx);
        float sm = e0 + e1;
#pragma unroll
        for (int o = 16; o > 0; o >>= 1) sm += __shfl_xor_sync(0xffffffff, sm, o);
        float inv = 1.f / sm;
        sc[w * 72 + lane] = e0 * inv;
        sc[w * 72 + lane + 32] = e1 * inv;
    }
    __syncthreads();

    // output: thread -> (h, d)
    {
        int h = tid >> 5, d = tid & 31;
        const float* ph = sc + h * 72;
        const __half* vb = kvs + 256 + h * HD + d;
        float acc = 0.f;
#pragma unroll
        for (int j = 0; j < WW; j++)
            acc = fmaf(ph[j], __half2float(vb[j * A2_KVS]), acc);
        out_h[(size_t)n * EE + h * HD + d] = __float2half(acc);
    }
}

// ---------------------------------------------------------------------------
// Head
// ---------------------------------------------------------------------------
__global__ void head_kernel(const float* __restrict__ y,
                            const float* __restrict__ hw,
                            const float* __restrict__ hb,
                            float* __restrict__ out) {
    int idx = blockIdx.x * blockDim.x + threadIdx.x;
    if (idx >= NWIN * OUTD) return;
    int n = idx / OUTD, o = idx % OUTD;
    const float* yr = y + (size_t)n * EE;
    const float* wr = hw + (size_t)o * EE;
    float acc = hb[o];
#pragma unroll 8
    for (int k = 0; k < EE; k++) acc = fmaf(yr[k], wr[k], acc);
    out[idx] = acc;
}

// ---------------------------------------------------------------------------
// Host launch
// ---------------------------------------------------------------------------
static inline dim3 tgrid(int M, int N) {
    return dim3(N / 128, (M + 127) / 128);
}

extern "C" void kernel_launch(void* const* d_in, const int* in_sizes, int n_in,
                              void* d_out, int out_size) {
    const float* inputs     = (const float*)d_in[0];
    const float* embed_w    = (const float*)d_in[1];
    const float* embed_b    = (const float*)d_in[2];
    const float* qkv_w      = (const float*)d_in[3];
    const float* qkv_b      = (const float*)d_in[4];
    const float* attn_out_w = (const float*)d_in[5];
    const float* attn_out_b = (const float*)d_in[6];
    const float* ln1_g      = (const float*)d_in[7];
    const float* ln1_b      = (const float*)d_in[8];
    const float* ffn1_w     = (const float*)d_in[9];
    const float* ffn1_b     = (const float*)d_in[10];
    const float* ffn2_w     = (const float*)d_in[11];
    const float* ffn2_b     = (const float*)d_in[12];
    const float* ln2_g      = (const float*)d_in[13];
    const float* ln2_b      = (const float*)d_in[14];
    const float* head_w     = (const float*)d_in[15];
    const float* head_b     = (const float*)d_in[16];
    float* out = (float*)d_out;

    cudaFuncSetAttribute(tgemm_ln, cudaFuncAttributeMaxDynamicSharedMemorySize, F_SMEM_BYTES);
    cudaFuncSetAttribute(attn2_kernel, cudaFuncAttributeMaxDynamicSharedMemorySize, A2_SMEM);

    float *emb, *bufA, *r1, *r2;
    __half *ew_h, *qw_h, *aw_h, *f1w_h, *f2w_h, *in_h;
    __half *emb_h, *qkv_h, *attn_h, *x_h, *ffh_h, *kv2_h, *r1_h, *r3_h;
    cudaGetSymbolAddress((void**)&emb,   g_emb);
    cudaGetSymbolAddress((void**)&bufA,  g_bufA);
    cudaGetSymbolAddress((void**)&r1,    g_r1);
    cudaGetSymbolAddress((void**)&r2,    g_r2);
    cudaGetSymbolAddress((void**)&in_h,   g_in_h);
    cudaGetSymbolAddress((void**)&ew_h,   g_ew_h);
    cudaGetSymbolAddress((void**)&qw_h,   g_qw_h);
    cudaGetSymbolAddress((void**)&aw_h,   g_aw_h);
    cudaGetSymbolAddress((void**)&f1w_h,  g_f1w_h);
    cudaGetSymbolAddress((void**)&f2w_h,  g_f2w_h);
    cudaGetSymbolAddress((void**)&emb_h,  g_emb_h);
    cudaGetSymbolAddress((void**)&qkv_h,  g_qkv_h);
    cudaGetSymbolAddress((void**)&attn_h, g_attn_h);
    cudaGetSymbolAddress((void**)&x_h,    g_x_h);
    cudaGetSymbolAddress((void**)&ffh_h,  g_ffh_h);
    cudaGetSymbolAddress((void**)&kv2_h,  g_kv2_h);
    cudaGetSymbolAddress((void**)&r1_h,   g_r1_h);
    cudaGetSymbolAddress((void**)&r3_h,   g_r3_h);

    // 0. fused fp16 conversions + pad zeroing (one launch)
    f2h_all_kernel<<<(N2_TOT + 255) / 256, 256>>>(
        (const float2*)inputs, (const float2*)embed_w, (const float2*)qkv_w,
        (const float2*)attn_out_w, (const float2*)ffn1_w, (const float2*)ffn2_w);

    // 1. embedding: single M=2048 GEMM, epilogue row-remap into padded layout
    tgemm_h<<<tgrid(BB * SS, EE), 256>>>(in_h, ew_h, embed_b, emb, emb_h,
                                         BB * SS, EE, FIN, FIN, FIN, EE, 0, 1);
    // 2. Layer-1 QKV (shared) -> fp16
    tgemm_h<<<tgrid(BB * PP, TE), 256>>>(emb_h, qw_h, qkv_b, (float*)0, qkv_h,
                                         BB * PP, TE, EE, EE, EE, TE, 0, 0);
    // 3. attention -> fp16
    attn1_kernel<<<dim3(NH, NWIN), 128>>>(qkv_h, attn_h);
    // 4+5. proj + LN1 fused -> bufA + x_h
    tgemm_ln<<<NROW / 128, 256, F_SMEM_BYTES>>>(attn_h, aw_h, attn_out_b, emb,
                                                ln1_g, ln1_b, bufA, x_h,
                                                NROW, EE, EE, EE, 1);
    // 6. FFN hidden (silu) -> fp16
    tgemm_h<<<tgrid(NROW, FF), 256>>>(x_h, f1w_h, ffn1_b, (float*)0, ffh_h,
                                      NROW, FF, EE, EE, EE, FF, 1, 0);
    // 7+8. FFN out + LN2 fused -> bufA + x_h
    tgemm_ln<<<NROW / 128, 256, F_SMEM_BYTES>>>(ffh_h, f2w_h, ffn2_b, bufA,
                                                ln2_g, ln2_b, bufA, x_h,
                                                NROW, FF, FF, FF, 0);

    // ---- Layer 2 (output pruned) ----
    // 9. Q for last rows only: A = strided last-row view of x_h
    tgemm_h<<<tgrid(NWIN, EE), 256>>>(x_h + (size_t)(WW - 1) * EE,
                                      qw_h + (size_t)TE * EE, qkv_b + TE,
                                      r2, (__half*)0, NWIN, EE, EE,
                                      WW * EE, EE, EE, 0, 0);
    // 10. KV for all rows -> fp16 kv2_h
    tgemm_h<<<tgrid(NROW, 512), 256>>>(x_h, qw_h + (size_t)TE * EE + (size_t)EE * EE,
                                       qkv_b + TE + EE, (float*)0, kv2_h,
                                       NROW, 512, EE, EE, EE, 512, 0, 0);
    // 11. attention (block per window) -> fp16 r1_h
    attn2_kernel<<<NWIN, 256, A2_SMEM>>>(r2, kv2_h, r1_h);
    // 12+13. proj + LN1_l2 fused -> r1 + r1_h (residual = bufA last rows, mode 2)
    tgemm_ln<<<NWIN / 128, 256, F_SMEM_BYTES>>>(r1_h, aw_h + (size_t)EE * EE,
                                                attn_out_b + EE, bufA,
                                                ln1_g + EE, ln1_b + EE, r1, r1_h,
                                                NWIN, EE, EE, EE, 2);
    // 14. h2 = silu(y @ W1^T) -> fp16 r3_h
    tgemm_h<<<tgrid(NWIN, FF), 256>>>(r1_h, f1w_h + (size_t)FF * EE, ffn1_b + FF,
                                      (float*)0, r3_h, NWIN, FF, EE, EE, EE, FF, 1, 0);
    // 15+16. FFN out + LN2_l2 fused -> r1
    tgemm_ln<<<NWIN / 128, 256, F_SMEM_BYTES>>>(r3_h, f2w_h + (size_t)EE * FF,
                                                ffn2_b + EE, r1,
                                                ln2_g + EE, ln2_b + EE, r1, (__half*)0,
                                                NWIN, FF, FF, FF, 0);
    // 17. head -> d_out
    head_kernel<<<(NWIN * OUTD + 255) / 256, 256>>>(r1, head_w, head_b, out);
}